// round 1
// baseline (speedup 1.0000x reference)
#include <cuda_runtime.h>
#include <math.h>

// Problem constants (fixed by the dataset)
#define NXC   32768
#define NTOT  66560          // 2*NX + J rows through both MLPs
#define DIMC  28
#define HC    300
#define FD    100            // dn output dim
#define GD    28             // an output dim
#define JC    1024

// ---------------- scratch (static __device__ — no allocs allowed) ----------
__device__ float g_in0 [(size_t)NTOT * DIMC];
__device__ float g_bufA[(size_t)NTOT * HC];
__device__ float g_bufB[(size_t)NTOT * HC];
__device__ float g_F   [(size_t)NTOT * FD];
__device__ float g_G   [(size_t)NTOT * GD];
__device__ float g_nF  [NTOT];
__device__ float g_nG  [NTOT];
__device__ float g_fm  [(size_t)NXC * JC];
__device__ float g_colsum[JC];
__device__ float g_mu    [JC];
__device__ float g_scal  [8];   // [0]=sum(fm^2) [1]=sum(s_i^2) [2]=sum(mu^2)

// ---------------- concat XY_tr and V into one activation buffer ------------
__global__ void concat_kernel(const float* __restrict__ XY, const float* __restrict__ V) {
    int t = blockIdx.x * blockDim.x + threadIdx.x;
    const int total = NTOT * DIMC;
    const int xyn   = 2 * NXC * DIMC;
    if (t >= total) return;
    g_in0[t] = (t < xyn) ? XY[t] : V[t - xyn];
}

__global__ void init_acc_kernel() {
    int t = threadIdx.x;
    if (t < JC) g_colsum[t] = 0.0f;
    if (t < 8)  g_scal[t]   = 0.0f;
}

// ---------------- SGEMM: C = act(A[N,Fi] @ W[Fi,Fo] + b) (+res) ------------
#define BM 128
#define BN 64
#define BK 16

__global__ __launch_bounds__(256)
void gemm_kernel(const float* __restrict__ A, const float* __restrict__ W,
                 const float* __restrict__ bias, float* __restrict__ C,
                 int Fi, int Fo, int doRelu, const float* __restrict__ res)
{
    __shared__ float As[BK][BM + 4];
    __shared__ float Bs[BK][BN];

    const int tid  = threadIdx.x;
    const int row0 = blockIdx.y * BM;
    const int col0 = blockIdx.x * BN;
    const int tx   = tid & 15;        // 16 col groups of 4
    const int ty   = tid >> 4;        // 16 row groups of 8

    float acc[8][4];
    #pragma unroll
    for (int i = 0; i < 8; i++)
        #pragma unroll
        for (int j = 0; j < 4; j++) acc[i][j] = 0.0f;

    const int nk = (Fi + BK - 1) / BK;
    for (int kt = 0; kt < nk; kt++) {
        const int k0 = kt * BK;
        // A tile: 128x16 (8 elems/thread), coalesced along k
        #pragma unroll
        for (int i = 0; i < 8; i++) {
            int e  = tid + 256 * i;
            int kk = e & (BK - 1);
            int r  = e >> 4;
            int gk = k0 + kk;
            As[kk][r] = (gk < Fi) ? A[(size_t)(row0 + r) * Fi + gk] : 0.0f;
        }
        // B tile: 16x64 (4 elems/thread), coalesced along columns
        #pragma unroll
        for (int i = 0; i < 4; i++) {
            int e  = tid + 256 * i;
            int kk = e >> 6;
            int c  = e & 63;
            int gk = k0 + kk, gc = col0 + c;
            Bs[kk][c] = (gk < Fi && gc < Fo) ? W[(size_t)gk * Fo + gc] : 0.0f;
        }
        __syncthreads();

        #pragma unroll
        for (int kk = 0; kk < BK; kk++) {
            float4 a0 = *(const float4*)&As[kk][ty * 8];
            float4 a1 = *(const float4*)&As[kk][ty * 8 + 4];
            float4 b  = *(const float4*)&Bs[kk][tx * 4];
            float av[8] = {a0.x, a0.y, a0.z, a0.w, a1.x, a1.y, a1.z, a1.w};
            float bv[4] = {b.x, b.y, b.z, b.w};
            #pragma unroll
            for (int i = 0; i < 8; i++)
                #pragma unroll
                for (int j = 0; j < 4; j++)
                    acc[i][j] += av[i] * bv[j];
        }
        __syncthreads();
    }

    #pragma unroll
    for (int j = 0; j < 4; j++) {
        int gc = col0 + tx * 4 + j;
        if (gc >= Fo) continue;
        float bb = bias[gc];
        #pragma unroll
        for (int i = 0; i < 8; i++) {
            int gr  = row0 + ty * 8 + i;
            float v = acc[i][j] + bb;
            if (res) v += res[(size_t)gr * Fo + gc];
            if (doRelu) v = fmaxf(v, 0.0f);
            C[(size_t)gr * Fo + gc] = v;
        }
    }
}

// ---------------- row squared norms ----------------------------------------
__global__ void row_norms_kernel(const float* __restrict__ X, float* __restrict__ out,
                                 int D, int n)
{
    int warp = (blockIdx.x * blockDim.x + threadIdx.x) >> 5;
    int lane = threadIdx.x & 31;
    if (warp >= n) return;
    float s = 0.0f;
    for (int k = lane; k < D; k += 32) {
        float v = X[(size_t)warp * D + k];
        s += v * v;
    }
    #pragma unroll
    for (int o = 16; o; o >>= 1) s += __shfl_xor_sync(0xffffffffu, s, o);
    if (lane == 0) out[warp] = s;
}

// ---------------- fm kernel: 32 i-rows x 128 j-cols per block --------------
// shared layout (floats): sFV[100*128] sGV[28*128] sFX[100*32] sFY[100*32]
//                         sGX[28*32] sGY[28*32] norms red
#define FM_SMEM_FLOATS 25088

__global__ __launch_bounds__(128)
void fm_kernel(const float* __restrict__ eps_p, const float* __restrict__ sig_p,
               const float* __restrict__ sig0_p, const float* __restrict__ cst_p)
{
    extern __shared__ float sm[];
    float* sFV = sm;             // 12800
    float* sGV = sm + 12800;     // 3584
    float* sFX = sm + 16384;     // 3200
    float* sFY = sm + 19584;     // 3200
    float* sGX = sm + 22784;     // 896
    float* sGY = sm + 23680;     // 896
    float* nfv = sm + 24576;     // 128
    float* ngv = sm + 24704;     // 128
    float* nfx = sm + 24832;     // 32
    float* nfy = sm + 24864;     // 32
    float* ngx = sm + 24896;     // 32
    float* ngy = sm + 24928;     // 32
    float* red = sm + 24960;     // 128

    const int tid   = threadIdx.x;
    const int jbase = blockIdx.x * 128;
    const int ibase = blockIdx.y * 32;
    const int YOFF  = NXC;
    const int VOFF  = 2 * NXC;

    // loads (coalesced along feature dim, transposed into shared)
    for (int e = tid; e < 128 * FD; e += 128) {
        int r = e / FD, k = e - r * FD;
        sFV[k * 128 + r] = g_F[(size_t)(VOFF + jbase + r) * FD + k];
    }
    for (int e = tid; e < 128 * GD; e += 128) {
        int r = e / GD, k = e - r * GD;
        sGV[k * 128 + r] = g_G[(size_t)(VOFF + jbase + r) * GD + k];
    }
    for (int e = tid; e < 32 * FD; e += 128) {
        int r = e / FD, k = e - r * FD;
        sFX[k * 32 + r] = g_F[(size_t)(ibase + r) * FD + k];
        sFY[k * 32 + r] = g_F[(size_t)(YOFF + ibase + r) * FD + k];
    }
    for (int e = tid; e < 32 * GD; e += 128) {
        int r = e / GD, k = e - r * GD;
        sGX[k * 32 + r] = g_G[(size_t)(ibase + r) * GD + k];
        sGY[k * 32 + r] = g_G[(size_t)(YOFF + ibase + r) * GD + k];
    }
    if (tid < 128) { nfv[tid] = g_nF[VOFF + jbase + tid]; ngv[tid] = g_nG[VOFF + jbase + tid]; }
    if (tid < 32)  {
        nfx[tid] = g_nF[ibase + tid];        nfy[tid] = g_nF[YOFF + ibase + tid];
        ngx[tid] = g_nG[ibase + tid];        ngy[tid] = g_nG[YOFF + ibase + tid];
    }
    __syncthreads();

    const float ep     = 1.0f / (1.0f + __expf(-eps_p[0]));
    const float inv_s  = 1.0f / (sig_p[0]  * sig_p[0]);
    const float inv_s0 = 1.0f / (sig0_p[0] * sig0_p[0]);
    const float cstv   = cst_p[0];
    const float one_ep = 1.0f - ep;
    const float RS     = 0.03125f;   // 1/sqrt(1024)

    const int ti = tid >> 4;         // 8 groups of 4 rows
    const int tj = tid & 15;         // 16 groups of 8 cols
    const int i0 = ti * 4;
    const int j0 = tj * 8;

    // ---- phase A: f-space dots (X and Y vs V) ----
    float dx[4][8], dy[4][8];
    #pragma unroll
    for (int a = 0; a < 4; a++)
        #pragma unroll
        for (int b = 0; b < 8; b++) { dx[a][b] = 0.0f; dy[a][b] = 0.0f; }

    #pragma unroll 2
    for (int k = 0; k < FD; k++) {
        float4 a4  = *(const float4*)(sFX + k * 32  + i0);
        float4 c4  = *(const float4*)(sFY + k * 32  + i0);
        float4 b40 = *(const float4*)(sFV + k * 128 + j0);
        float4 b41 = *(const float4*)(sFV + k * 128 + j0 + 4);
        float av[4] = {a4.x, a4.y, a4.z, a4.w};
        float cv[4] = {c4.x, c4.y, c4.z, c4.w};
        float bv[8] = {b40.x, b40.y, b40.z, b40.w, b41.x, b41.y, b41.z, b41.w};
        #pragma unroll
        for (int ii = 0; ii < 4; ii++)
            #pragma unroll
            for (int jj = 0; jj < 8; jj++) {
                dx[ii][jj] += av[ii] * bv[jj];
                dy[ii][jj] += cv[ii] * bv[jj];
            }
    }
    // convert dots -> gaussian-kernel f-factor in place
    #pragma unroll
    for (int ii = 0; ii < 4; ii++)
        #pragma unroll
        for (int jj = 0; jj < 8; jj++) {
            float Dx = fmaxf(nfx[i0 + ii] + nfv[j0 + jj] - 2.0f * dx[ii][jj], 0.0f);
            float Dy = fmaxf(nfy[i0 + ii] + nfv[j0 + jj] - 2.0f * dy[ii][jj], 0.0f);
            dx[ii][jj] = one_ep * __expf(-Dx * inv_s0) + ep;
            dy[ii][jj] = one_ep * __expf(-Dy * inv_s0) + ep;
        }

    // ---- phase B: g-space dots ----
    float gx[4][8], gy[4][8];
    #pragma unroll
    for (int a = 0; a < 4; a++)
        #pragma unroll
        for (int b = 0; b < 8; b++) { gx[a][b] = 0.0f; gy[a][b] = 0.0f; }

    #pragma unroll
    for (int k = 0; k < GD; k++) {
        float4 a4  = *(const float4*)(sGX + k * 32  + i0);
        float4 c4  = *(const float4*)(sGY + k * 32  + i0);
        float4 b40 = *(const float4*)(sGV + k * 128 + j0);
        float4 b41 = *(const float4*)(sGV + k * 128 + j0 + 4);
        float av[4] = {a4.x, a4.y, a4.z, a4.w};
        float cv[4] = {c4.x, c4.y, c4.z, c4.w};
        float bv[8] = {b40.x, b40.y, b40.z, b40.w, b41.x, b41.y, b41.z, b41.w};
        #pragma unroll
        for (int ii = 0; ii < 4; ii++)
            #pragma unroll
            for (int jj = 0; jj < 8; jj++) {
                gx[ii][jj] += av[ii] * bv[jj];
                gy[ii][jj] += cv[ii] * bv[jj];
            }
    }

    // ---- epilogue: fm values, column sums, sum of squares ----
    float csum[8];
    #pragma unroll
    for (int jj = 0; jj < 8; jj++) csum[jj] = 0.0f;
    float q = 0.0f;

    #pragma unroll
    for (int ii = 0; ii < 4; ii++) {
        float vout[8];
        #pragma unroll
        for (int jj = 0; jj < 8; jj++) {
            float Dgx = fmaxf(ngx[i0 + ii] + ngv[j0 + jj] - 2.0f * gx[ii][jj], 0.0f);
            float Dgy = fmaxf(ngy[i0 + ii] + ngv[j0 + jj] - 2.0f * gy[ii][jj], 0.0f);
            float KX  = cstv * dx[ii][jj] * __expf(-Dgx * inv_s);
            float KY  = cstv * dy[ii][jj] * __expf(-Dgy * inv_s);
            float v   = (KX - KY) * RS;
            vout[jj] = v;
            csum[jj] += v;
            q += v * v;
        }
        size_t base = (size_t)(ibase + i0 + ii) * JC + jbase + j0;
        *(float4*)(g_fm + base)     = make_float4(vout[0], vout[1], vout[2], vout[3]);
        *(float4*)(g_fm + base + 4) = make_float4(vout[4], vout[5], vout[6], vout[7]);
    }
    #pragma unroll
    for (int jj = 0; jj < 8; jj++)
        atomicAdd(&g_colsum[jbase + j0 + jj], csum[jj]);

    red[tid] = q;
    __syncthreads();
    for (int s = 64; s; s >>= 1) {
        if (tid < s) red[tid] += red[tid + s];
        __syncthreads();
    }
    if (tid == 0) atomicAdd(&g_scal[0], red[0]);
}

// ---------------- mu + sum(mu^2) --------------------------------------------
__global__ void mu_kernel() {
    __shared__ float red[JC];
    int j = threadIdx.x;
    float m = g_colsum[j] * (1.0f / (float)NXC);
    g_mu[j] = m;
    red[j] = m * m;
    __syncthreads();
    for (int s = 512; s; s >>= 1) {
        if (j < s) red[j] += red[j + s];
        __syncthreads();
    }
    if (j == 0) g_scal[2] = red[0];
}

// ---------------- s_i = fm[i]·mu ; accumulate s_i^2 -------------------------
__global__ __launch_bounds__(256) void s2_kernel() {
    __shared__ float smu[JC];
    int tid = threadIdx.x;
    for (int e = tid; e < JC; e += 256) smu[e] = g_mu[e];
    __syncthreads();
    int row  = blockIdx.x * 8 + (tid >> 5);
    int lane = tid & 31;
    float s = 0.0f;
    #pragma unroll 4
    for (int t = 0; t < 32; t++) {
        int c = lane + 32 * t;
        s += g_fm[(size_t)row * JC + c] * smu[c];
    }
    #pragma unroll
    for (int o = 16; o; o >>= 1) s += __shfl_xor_sync(0xffffffffu, s, o);
    if (lane == 0) atomicAdd(&g_scal[1], s * s);
}

// ---------------- finalize (fp64 to kill cancellation) ----------------------
__global__ void finalize_kernel(float* out) {
    double sumfm2 = (double)g_scal[0];
    double sums2  = (double)g_scal[1];
    double summu2 = (double)g_scal[2];
    double nx = (double)NXC;
    double t1 = summu2 * (nx / (nx - 1.0));
    double t2 = sumfm2 / nx / (nx - 1.0);
    double mean = t1 - t2;
    double var  = 4.0 * (sums2 / nx) - 4.0 * summu2 * summu2;
    out[0] = (float)(-(mean / sqrt(var + 1e-6)));
}

// ---------------- launch -----------------------------------------------------
extern "C" void kernel_launch(void* const* d_in, const int* in_sizes, int n_in,
                              void* d_out, int out_size)
{
    const float* XY = (const float*)d_in[0];
    const float* V  = (const float*)d_in[1];
    const float *dnW[6], *dnb[6], *anW[6], *anb[6];
    for (int i = 0; i < 6; i++) {
        dnW[i] = (const float*)d_in[2 + 2 * i];
        dnb[i] = (const float*)d_in[3 + 2 * i];
        anW[i] = (const float*)d_in[14 + 2 * i];
        anb[i] = (const float*)d_in[15 + 2 * i];
    }
    const float* eps   = (const float*)d_in[26];
    const float* sig   = (const float*)d_in[27];
    const float* sig0  = (const float*)d_in[28];
    const float* cstp  = (const float*)d_in[29];

    float *in0, *bufA, *bufB, *F, *G, *nF, *nG;
    cudaGetSymbolAddress((void**)&in0,  g_in0);
    cudaGetSymbolAddress((void**)&bufA, g_bufA);
    cudaGetSymbolAddress((void**)&bufB, g_bufB);
    cudaGetSymbolAddress((void**)&F,    g_F);
    cudaGetSymbolAddress((void**)&G,    g_G);
    cudaGetSymbolAddress((void**)&nF,   g_nF);
    cudaGetSymbolAddress((void**)&nG,   g_nG);

    static_assert(NTOT % BM == 0, "rows must tile");
    const int GY = NTOT / BM;                   // 520
    const dim3 blk(256);
    const dim3 gH  ((HC  + BN - 1) / BN, GY);   // Fo=300 -> 5 x 520
    const dim3 gF  ((FD  + BN - 1) / BN, GY);   // Fo=100 -> 2 x 520
    const dim3 gG  ((GD  + BN - 1) / BN, GY);   // Fo=28  -> 1 x 520

    // concat + accumulator reset
    concat_kernel<<<(NTOT * DIMC + 255) / 256, 256>>>(XY, V);
    init_acc_kernel<<<1, 1024>>>();

    // dn MLP
    gemm_kernel<<<gH, blk>>>(in0,  dnW[0], dnb[0], bufA, DIMC, HC, 1, nullptr);
    gemm_kernel<<<gH, blk>>>(bufA, dnW[1], dnb[1], bufB, HC,   HC, 1, nullptr);
    gemm_kernel<<<gH, blk>>>(bufB, dnW[2], dnb[2], bufA, HC,   HC, 1, nullptr);
    gemm_kernel<<<gH, blk>>>(bufA, dnW[3], dnb[3], bufB, HC,   HC, 1, nullptr);
    gemm_kernel<<<gH, blk>>>(bufB, dnW[4], dnb[4], bufA, HC,   HC, 1, nullptr);
    gemm_kernel<<<gF, blk>>>(bufA, dnW[5], dnb[5], F,    HC,   FD, 0, nullptr);

    // an MLP (residual on last layer)
    gemm_kernel<<<gH, blk>>>(in0,  anW[0], anb[0], bufA, DIMC, HC, 1, nullptr);
    gemm_kernel<<<gH, blk>>>(bufA, anW[1], anb[1], bufB, HC,   HC, 1, nullptr);
    gemm_kernel<<<gH, blk>>>(bufB, anW[2], anb[2], bufA, HC,   HC, 1, nullptr);
    gemm_kernel<<<gH, blk>>>(bufA, anW[3], anb[3], bufB, HC,   HC, 1, nullptr);
    gemm_kernel<<<gH, blk>>>(bufB, anW[4], anb[4], bufA, HC,   HC, 1, nullptr);
    gemm_kernel<<<gG, blk>>>(bufA, anW[5], anb[5], G,    HC,   GD, 0, in0);

    // row norms
    row_norms_kernel<<<NTOT / 8, 256>>>(F, nF, FD, NTOT);
    row_norms_kernel<<<NTOT / 8, 256>>>(G, nG, GD, NTOT);

    // fm + partial reductions
    cudaFuncSetAttribute(fm_kernel, cudaFuncAttributeMaxDynamicSharedMemorySize,
                         FM_SMEM_FLOATS * (int)sizeof(float));
    fm_kernel<<<dim3(JC / 128, NXC / 32), 128, FM_SMEM_FLOATS * sizeof(float)>>>(
        eps, sig, sig0, cstp);

    // mu, s^2, final scalar
    mu_kernel<<<1, JC>>>();
    s2_kernel<<<NXC / 8, 256>>>();
    finalize_kernel<<<1, 1>>>((float*)d_out);
}

// round 3
// speedup vs baseline: 1.7288x; 1.7288x over previous
#include <cuda_runtime.h>
#include <cuda_bf16.h>
#include <math.h>
#include <stdint.h>

// Problem constants (fixed by the dataset)
#define NXC   32768
#define NTOT  66560          // 2*NX + J rows through both MLPs
#define DIMC  28
#define HC    300
#define FD    100            // dn output dim
#define GD    28             // an output dim
#define JC    1024

// ---------------- scratch (static __device__ — no allocs allowed) ----------
__device__ float g_in0 [(size_t)NTOT * DIMC];
__device__ float g_bufA[(size_t)NTOT * HC];
__device__ float g_bufB[(size_t)NTOT * HC];
__device__ float g_F   [(size_t)NTOT * FD];
__device__ float g_G   [(size_t)NTOT * GD];
__device__ float g_nF  [NTOT];
__device__ float g_nG  [NTOT];
__device__ float g_fm  [(size_t)NXC * JC];
__device__ float g_colsum[JC];
__device__ float g_mu    [JC];
__device__ float g_scal  [8];   // [0]=sum(fm^2) [1]=sum(s_i^2) [2]=sum(mu^2)

// ---------------- concat XY_tr and V into one activation buffer ------------
__global__ void concat_kernel(const float* __restrict__ XY, const float* __restrict__ V) {
    int t = blockIdx.x * blockDim.x + threadIdx.x;
    const int total = NTOT * DIMC;
    const int xyn   = 2 * NXC * DIMC;
    if (t >= total) return;
    g_in0[t] = (t < xyn) ? XY[t] : V[t - xyn];
}

__global__ void init_acc_kernel() {
    int t = threadIdx.x;
    if (t < JC) g_colsum[t] = 0.0f;
    if (t < 8)  g_scal[t]   = 0.0f;
}

// =============== legacy-mma bf16-split GEMM (no tcgen05) ====================
// C[BM=128 x BN=64] per CTA, 8 warps of 32x32, mma.m16n8k16 bf16 with 2-way
// split + 4 cross products accumulated in fp32 (≈fp32 accuracy).

#define BMM 128
#define BNN 64
#define BKK 32
#define A_STRIDE 40     // 32 + 8 pad (bf16): conflict-free ldmatrix rows
#define B_STRIDE 72     // 64 + 8 pad (bf16): conflict-free ldmatrix.trans

__device__ __forceinline__ uint32_t smem_u32(const void* p) {
    uint32_t a;
    asm("{ .reg .u64 t; cvta.to.shared.u64 t, %1; cvt.u32.u64 %0, t; }" : "=r"(a) : "l"(p));
    return a;
}
__device__ __forceinline__ void ldsm_x4(uint32_t addr, uint32_t r[4]) {
    asm volatile("ldmatrix.sync.aligned.m8n8.x4.shared.b16 {%0,%1,%2,%3}, [%4];"
        : "=r"(r[0]), "=r"(r[1]), "=r"(r[2]), "=r"(r[3]) : "r"(addr));
}
__device__ __forceinline__ void ldsm_x4_t(uint32_t addr, uint32_t r[4]) {
    asm volatile("ldmatrix.sync.aligned.m8n8.x4.trans.shared.b16 {%0,%1,%2,%3}, [%4];"
        : "=r"(r[0]), "=r"(r[1]), "=r"(r[2]), "=r"(r[3]) : "r"(addr));
}
__device__ __forceinline__ void mma_bf16(float c[4], const uint32_t a[4],
                                         uint32_t b0, uint32_t b1) {
    asm volatile(
        "mma.sync.aligned.m16n8k16.row.col.f32.bf16.bf16.f32 "
        "{%0,%1,%2,%3}, {%4,%5,%6,%7}, {%8,%9}, {%0,%1,%2,%3};"
        : "+f"(c[0]), "+f"(c[1]), "+f"(c[2]), "+f"(c[3])
        : "r"(a[0]), "r"(a[1]), "r"(a[2]), "r"(a[3]), "r"(b0), "r"(b1));
}
__device__ __forceinline__ void split2(float x, __nv_bfloat16& h, __nv_bfloat16& l) {
    h = __float2bfloat16(x);
    l = __float2bfloat16(x - __bfloat162float(h));
}

__global__ __launch_bounds__(256)
void mma_gemm_kernel(const float* __restrict__ A, const float* __restrict__ W,
                     const float* __restrict__ bias, float* __restrict__ C,
                     const float* __restrict__ res,
                     int Fi, int Fo, int nC, int doRelu)
{
    __shared__ __nv_bfloat16 sAh[BMM * A_STRIDE];
    __shared__ __nv_bfloat16 sAl[BMM * A_STRIDE];
    __shared__ __nv_bfloat16 sBh[BKK * B_STRIDE];
    __shared__ __nv_bfloat16 sBl[BKK * B_STRIDE];

    const int tid    = threadIdx.x;
    const int lane   = tid & 31;
    const int wid    = tid >> 5;
    const int warp_m = wid >> 1;       // 0..3 (32 rows each)
    const int warp_n = wid & 1;        // 0..1 (32 cols each)
    const int rbase  = blockIdx.y * BMM;
    const int n0     = blockIdx.x * BNN;

    // global-load lane mapping
    const int ar = tid >> 3;           // 0..31 (A rows, +32*i)
    const int ak = (tid & 7) * 4;      // 0..28 (A k within chunk)
    const int bk = tid >> 3;           // 0..31 (B k rows)
    const int bn = (tid & 7) * 4;      // 0..28 (B n within 32, +32*i)

    // ldmatrix base addresses (add per-(mi,ks) offsets in loop)
    const uint32_t sAh32 = smem_u32(sAh), sAl32 = smem_u32(sAl);
    const uint32_t sBh32 = smem_u32(sBh), sBl32 = smem_u32(sBl);
    const int a_row  = warp_m * 32 + (lane & 15);
    const int a_kadd = (lane >> 4) * 8;
    const uint32_t aHiB = sAh32 + (uint32_t)(a_row * A_STRIDE + a_kadd) * 2u;
    const uint32_t aLoB = sAl32 + (uint32_t)(a_row * A_STRIDE + a_kadd) * 2u;
    const int b_k = (lane & 7) + ((lane & 8) ? 8 : 0);
    const int b_n = warp_n * 32 + ((lane & 16) ? 8 : 0);
    const uint32_t bHiB = sBh32 + (uint32_t)(b_k * B_STRIDE + b_n) * 2u;
    const uint32_t bLoB = sBl32 + (uint32_t)(b_k * B_STRIDE + b_n) * 2u;

    float acc[2][4][4];
    #pragma unroll
    for (int i = 0; i < 2; i++)
        #pragma unroll
        for (int j = 0; j < 4; j++)
            #pragma unroll
            for (int q = 0; q < 4; q++) acc[i][j][q] = 0.0f;

    float4 pa[4], pb[2];
    const float4 z4 = make_float4(0.f, 0.f, 0.f, 0.f);

    // prologue: load chunk 0
    {
        const int gk = ak;  // k0 = 0
        #pragma unroll
        for (int i = 0; i < 4; i++) {
            int row = rbase + ar + 32 * i;
            pa[i] = (gk < Fi) ? *(const float4*)(A + (size_t)row * Fi + gk) : z4;
        }
        #pragma unroll
        for (int i = 0; i < 2; i++) {
            int gn = n0 + bn + 32 * i;
            pb[i] = (bk < Fi && gn < Fo) ? *(const float4*)(W + (size_t)bk * Fo + gn) : z4;
        }
    }

    for (int c = 0; c < nC; c++) {
        // store prefetched chunk to smem (split hi/lo)
        #pragma unroll
        for (int i = 0; i < 4; i++) {
            int r = ar + 32 * i;
            __nv_bfloat16 h0, l0, h1, l1, h2, l2, h3, l3;
            split2(pa[i].x, h0, l0); split2(pa[i].y, h1, l1);
            split2(pa[i].z, h2, l2); split2(pa[i].w, h3, l3);
            *(__nv_bfloat162*)&sAh[r * A_STRIDE + ak]     = __halves2bfloat162(h0, h1);
            *(__nv_bfloat162*)&sAh[r * A_STRIDE + ak + 2] = __halves2bfloat162(h2, h3);
            *(__nv_bfloat162*)&sAl[r * A_STRIDE + ak]     = __halves2bfloat162(l0, l1);
            *(__nv_bfloat162*)&sAl[r * A_STRIDE + ak + 2] = __halves2bfloat162(l2, l3);
        }
        #pragma unroll
        for (int i = 0; i < 2; i++) {
            int nn = bn + 32 * i;
            __nv_bfloat16 h0, l0, h1, l1, h2, l2, h3, l3;
            split2(pb[i].x, h0, l0); split2(pb[i].y, h1, l1);
            split2(pb[i].z, h2, l2); split2(pb[i].w, h3, l3);
            *(__nv_bfloat162*)&sBh[bk * B_STRIDE + nn]     = __halves2bfloat162(h0, h1);
            *(__nv_bfloat162*)&sBh[bk * B_STRIDE + nn + 2] = __halves2bfloat162(h2, h3);
            *(__nv_bfloat162*)&sBl[bk * B_STRIDE + nn]     = __halves2bfloat162(l0, l1);
            *(__nv_bfloat162*)&sBl[bk * B_STRIDE + nn + 2] = __halves2bfloat162(l2, l3);
        }
        __syncthreads();

        // prefetch next chunk (overlaps with MMA below)
        if (c + 1 < nC) {
            const int k0 = (c + 1) * BKK;
            const int gk = k0 + ak;
            #pragma unroll
            for (int i = 0; i < 4; i++) {
                int row = rbase + ar + 32 * i;
                pa[i] = (gk < Fi) ? *(const float4*)(A + (size_t)row * Fi + gk) : z4;
            }
            const int gkb = k0 + bk;
            #pragma unroll
            for (int i = 0; i < 2; i++) {
                int gn = n0 + bn + 32 * i;
                pb[i] = (gkb < Fi && gn < Fo) ? *(const float4*)(W + (size_t)gkb * Fo + gn) : z4;
            }
        }

        // MMA over this chunk: 2 ksteps of 16
        #pragma unroll
        for (int ks = 0; ks < 2; ks++) {
            uint32_t Ah[2][4], Al[2][4], Bh[2][4], Bl[2][4];
            #pragma unroll
            for (int mi = 0; mi < 2; mi++) {
                uint32_t off = (uint32_t)(mi * 16 * A_STRIDE + ks * 16) * 2u;
                ldsm_x4(aHiB + off, Ah[mi]);
                ldsm_x4(aLoB + off, Al[mi]);
            }
            #pragma unroll
            for (int np = 0; np < 2; np++) {
                uint32_t off = (uint32_t)(np * 16 + ks * 16 * B_STRIDE) * 2u;
                ldsm_x4_t(bHiB + off, Bh[np]);
                ldsm_x4_t(bLoB + off, Bl[np]);
            }
            #pragma unroll
            for (int mi = 0; mi < 2; mi++)
                #pragma unroll
                for (int nj = 0; nj < 4; nj++) {
                    const int np = nj >> 1, hf = (nj & 1) * 2;
                    mma_bf16(acc[mi][nj], Ah[mi], Bh[np][hf], Bh[np][hf + 1]);
                    mma_bf16(acc[mi][nj], Ah[mi], Bl[np][hf], Bl[np][hf + 1]);
                    mma_bf16(acc[mi][nj], Al[mi], Bh[np][hf], Bh[np][hf + 1]);
                    mma_bf16(acc[mi][nj], Al[mi], Bl[np][hf], Bl[np][hf + 1]);
                }
        }
        __syncthreads();
    }

    // epilogue
    #pragma unroll
    for (int mi = 0; mi < 2; mi++)
        #pragma unroll
        for (int nj = 0; nj < 4; nj++) {
            int col = n0 + warp_n * 32 + nj * 8 + (lane & 3) * 2;
            if (col >= Fo) continue;
            float2 b2 = *(const float2*)(bias + col);
            #pragma unroll
            for (int half = 0; half < 2; half++) {
                int row = rbase + warp_m * 32 + mi * 16 + (lane >> 2) + half * 8;
                float vx = acc[mi][nj][half * 2 + 0] + b2.x;
                float vy = acc[mi][nj][half * 2 + 1] + b2.y;
                if (res) {
                    float2 r2 = *(const float2*)(res + (size_t)row * Fo + col);
                    vx += r2.x; vy += r2.y;
                }
                if (doRelu) { vx = fmaxf(vx, 0.0f); vy = fmaxf(vy, 0.0f); }
                *(float2*)(C + (size_t)row * Fo + col) = make_float2(vx, vy);
            }
        }
}

// ---------------- row squared norms ----------------------------------------
__global__ void row_norms_kernel(const float* __restrict__ X, float* __restrict__ out,
                                 int D, int n)
{
    int warp = (blockIdx.x * blockDim.x + threadIdx.x) >> 5;
    int lane = threadIdx.x & 31;
    if (warp >= n) return;
    float s = 0.0f;
    for (int k = lane; k < D; k += 32) {
        float v = X[(size_t)warp * D + k];
        s += v * v;
    }
    #pragma unroll
    for (int o = 16; o; o >>= 1) s += __shfl_xor_sync(0xffffffffu, s, o);
    if (lane == 0) out[warp] = s;
}

// ---------------- fm kernel: 32 i-rows x 128 j-cols per block --------------
#define FM_SMEM_FLOATS 25088

__global__ __launch_bounds__(128)
void fm_kernel(const float* __restrict__ eps_p, const float* __restrict__ sig_p,
               const float* __restrict__ sig0_p, const float* __restrict__ cst_p)
{
    extern __shared__ float sm[];
    float* sFV = sm;             // 12800
    float* sGV = sm + 12800;     // 3584
    float* sFX = sm + 16384;     // 3200
    float* sFY = sm + 19584;     // 3200
    float* sGX = sm + 22784;     // 896
    float* sGY = sm + 23680;     // 896
    float* nfv = sm + 24576;     // 128
    float* ngv = sm + 24704;     // 128
    float* nfx = sm + 24832;     // 32
    float* nfy = sm + 24864;     // 32
    float* ngx = sm + 24896;     // 32
    float* ngy = sm + 24928;     // 32
    float* red = sm + 24960;     // 128

    const int tid   = threadIdx.x;
    const int jbase = blockIdx.x * 128;
    const int ibase = blockIdx.y * 32;
    const int YOFF  = NXC;
    const int VOFF  = 2 * NXC;

    for (int e = tid; e < 128 * FD; e += 128) {
        int r = e / FD, k = e - r * FD;
        sFV[k * 128 + r] = g_F[(size_t)(VOFF + jbase + r) * FD + k];
    }
    for (int e = tid; e < 128 * GD; e += 128) {
        int r = e / GD, k = e - r * GD;
        sGV[k * 128 + r] = g_G[(size_t)(VOFF + jbase + r) * GD + k];
    }
    for (int e = tid; e < 32 * FD; e += 128) {
        int r = e / FD, k = e - r * FD;
        sFX[k * 32 + r] = g_F[(size_t)(ibase + r) * FD + k];
        sFY[k * 32 + r] = g_F[(size_t)(YOFF + ibase + r) * FD + k];
    }
    for (int e = tid; e < 32 * GD; e += 128) {
        int r = e / GD, k = e - r * GD;
        sGX[k * 32 + r] = g_G[(size_t)(ibase + r) * GD + k];
        sGY[k * 32 + r] = g_G[(size_t)(YOFF + ibase + r) * GD + k];
    }
    if (tid < 128) { nfv[tid] = g_nF[VOFF + jbase + tid]; ngv[tid] = g_nG[VOFF + jbase + tid]; }
    if (tid < 32)  {
        nfx[tid] = g_nF[ibase + tid];        nfy[tid] = g_nF[YOFF + ibase + tid];
        ngx[tid] = g_nG[ibase + tid];        ngy[tid] = g_nG[YOFF + ibase + tid];
    }
    __syncthreads();

    const float ep     = 1.0f / (1.0f + __expf(-eps_p[0]));
    const float inv_s  = 1.0f / (sig_p[0]  * sig_p[0]);
    const float inv_s0 = 1.0f / (sig0_p[0] * sig0_p[0]);
    const float cstv   = cst_p[0];
    const float one_ep = 1.0f - ep;
    const float RS     = 0.03125f;   // 1/sqrt(1024)

    const int ti = tid >> 4;
    const int tj = tid & 15;
    const int i0 = ti * 4;
    const int j0 = tj * 8;

    float dx[4][8], dy[4][8];
    #pragma unroll
    for (int a = 0; a < 4; a++)
        #pragma unroll
        for (int b = 0; b < 8; b++) { dx[a][b] = 0.0f; dy[a][b] = 0.0f; }

    #pragma unroll 2
    for (int k = 0; k < FD; k++) {
        float4 a4  = *(const float4*)(sFX + k * 32  + i0);
        float4 c4  = *(const float4*)(sFY + k * 32  + i0);
        float4 b40 = *(const float4*)(sFV + k * 128 + j0);
        float4 b41 = *(const float4*)(sFV + k * 128 + j0 + 4);
        float av[4] = {a4.x, a4.y, a4.z, a4.w};
        float cv[4] = {c4.x, c4.y, c4.z, c4.w};
        float bv[8] = {b40.x, b40.y, b40.z, b40.w, b41.x, b41.y, b41.z, b41.w};
        #pragma unroll
        for (int ii = 0; ii < 4; ii++)
            #pragma unroll
            for (int jj = 0; jj < 8; jj++) {
                dx[ii][jj] += av[ii] * bv[jj];
                dy[ii][jj] += cv[ii] * bv[jj];
            }
    }
    #pragma unroll
    for (int ii = 0; ii < 4; ii++)
        #pragma unroll
        for (int jj = 0; jj < 8; jj++) {
            float Dx = fmaxf(nfx[i0 + ii] + nfv[j0 + jj] - 2.0f * dx[ii][jj], 0.0f);
            float Dy = fmaxf(nfy[i0 + ii] + nfv[j0 + jj] - 2.0f * dy[ii][jj], 0.0f);
            dx[ii][jj] = one_ep * __expf(-Dx * inv_s0) + ep;
            dy[ii][jj] = one_ep * __expf(-Dy * inv_s0) + ep;
        }

    float gx[4][8], gy[4][8];
    #pragma unroll
    for (int a = 0; a < 4; a++)
        #pragma unroll
        for (int b = 0; b < 8; b++) { gx[a][b] = 0.0f; gy[a][b] = 0.0f; }

    #pragma unroll
    for (int k = 0; k < GD; k++) {
        float4 a4  = *(const float4*)(sGX + k * 32  + i0);
        float4 c4  = *(const float4*)(sGY + k * 32  + i0);
        float4 b40 = *(const float4*)(sGV + k * 128 + j0);
        float4 b41 = *(const float4*)(sGV + k * 128 + j0 + 4);
        float av[4] = {a4.x, a4.y, a4.z, a4.w};
        float cv[4] = {c4.x, c4.y, c4.z, c4.w};
        float bv[8] = {b40.x, b40.y, b40.z, b40.w, b41.x, b41.y, b41.z, b41.w};
        #pragma unroll
        for (int ii = 0; ii < 4; ii++)
            #pragma unroll
            for (int jj = 0; jj < 8; jj++) {
                gx[ii][jj] += av[ii] * bv[jj];
                gy[ii][jj] += cv[ii] * bv[jj];
            }
    }

    float csum[8];
    #pragma unroll
    for (int jj = 0; jj < 8; jj++) csum[jj] = 0.0f;
    float q = 0.0f;

    #pragma unroll
    for (int ii = 0; ii < 4; ii++) {
        float vout[8];
        #pragma unroll
        for (int jj = 0; jj < 8; jj++) {
            float Dgx = fmaxf(ngx[i0 + ii] + ngv[j0 + jj] - 2.0f * gx[ii][jj], 0.0f);
            float Dgy = fmaxf(ngy[i0 + ii] + ngv[j0 + jj] - 2.0f * gy[ii][jj], 0.0f);
            float KX  = cstv * dx[ii][jj] * __expf(-Dgx * inv_s);
            float KY  = cstv * dy[ii][jj] * __expf(-Dgy * inv_s);
            float v   = (KX - KY) * RS;
            vout[jj] = v;
            csum[jj] += v;
            q += v * v;
        }
        size_t basei = (size_t)(ibase + i0 + ii) * JC + jbase + j0;
        *(float4*)(g_fm + basei)     = make_float4(vout[0], vout[1], vout[2], vout[3]);
        *(float4*)(g_fm + basei + 4) = make_float4(vout[4], vout[5], vout[6], vout[7]);
    }
    #pragma unroll
    for (int jj = 0; jj < 8; jj++)
        atomicAdd(&g_colsum[jbase + j0 + jj], csum[jj]);

    red[tid] = q;
    __syncthreads();
    for (int s = 64; s; s >>= 1) {
        if (tid < s) red[tid] += red[tid + s];
        __syncthreads();
    }
    if (tid == 0) atomicAdd(&g_scal[0], red[0]);
}

// ---------------- mu + sum(mu^2) --------------------------------------------
__global__ void mu_kernel() {
    __shared__ float red[JC];
    int j = threadIdx.x;
    float m = g_colsum[j] * (1.0f / (float)NXC);
    g_mu[j] = m;
    red[j] = m * m;
    __syncthreads();
    for (int s = 512; s; s >>= 1) {
        if (j < s) red[j] += red[j + s];
        __syncthreads();
    }
    if (j == 0) g_scal[2] = red[0];
}

// ---------------- s_i = fm[i]·mu ; accumulate s_i^2 -------------------------
__global__ __launch_bounds__(256) void s2_kernel() {
    __shared__ float smu[JC];
    int tid = threadIdx.x;
    for (int e = tid; e < JC; e += 256) smu[e] = g_mu[e];
    __syncthreads();
    int row  = blockIdx.x * 8 + (tid >> 5);
    int lane = tid & 31;
    float s = 0.0f;
    #pragma unroll 4
    for (int t = 0; t < 32; t++) {
        int c = lane + 32 * t;
        s += g_fm[(size_t)row * JC + c] * smu[c];
    }
    #pragma unroll
    for (int o = 16; o; o >>= 1) s += __shfl_xor_sync(0xffffffffu, s, o);
    if (lane == 0) atomicAdd(&g_scal[1], s * s);
}

// ---------------- finalize (fp64 to kill cancellation) ----------------------
__global__ void finalize_kernel(float* out) {
    double sumfm2 = (double)g_scal[0];
    double sums2  = (double)g_scal[1];
    double summu2 = (double)g_scal[2];
    double nx = (double)NXC;
    double t1 = summu2 * (nx / (nx - 1.0));
    double t2 = sumfm2 / nx / (nx - 1.0);
    double mean = t1 - t2;
    double var  = 4.0 * (sums2 / nx) - 4.0 * summu2 * summu2;
    out[0] = (float)(-(mean / sqrt(var + 1e-6)));
}

// ---------------- launch -----------------------------------------------------
extern "C" void kernel_launch(void* const* d_in, const int* in_sizes, int n_in,
                              void* d_out, int out_size)
{
    const float* XY = (const float*)d_in[0];
    const float* V  = (const float*)d_in[1];
    const float *dnW[6], *dnb[6], *anW[6], *anb[6];
    for (int i = 0; i < 6; i++) {
        dnW[i] = (const float*)d_in[2 + 2 * i];
        dnb[i] = (const float*)d_in[3 + 2 * i];
        anW[i] = (const float*)d_in[14 + 2 * i];
        anb[i] = (const float*)d_in[15 + 2 * i];
    }
    const float* eps   = (const float*)d_in[26];
    const float* sig   = (const float*)d_in[27];
    const float* sig0  = (const float*)d_in[28];
    const float* cstp  = (const float*)d_in[29];

    float *in0, *bufA, *bufB, *F, *G, *nF, *nG;
    cudaGetSymbolAddress((void**)&in0,  g_in0);
    cudaGetSymbolAddress((void**)&bufA, g_bufA);
    cudaGetSymbolAddress((void**)&bufB, g_bufB);
    cudaGetSymbolAddress((void**)&F,    g_F);
    cudaGetSymbolAddress((void**)&G,    g_G);
    cudaGetSymbolAddress((void**)&nF,   g_nF);
    cudaGetSymbolAddress((void**)&nG,   g_nG);

    const int GY = NTOT / BMM;                       // 520
    const dim3 blk(256);
    const dim3 gH((HC + BNN - 1) / BNN, GY);         // 5 x 520
    const dim3 gF((FD + BNN - 1) / BNN, GY);         // 2 x 520
    const dim3 gG((GD + BNN - 1) / BNN, GY);         // 1 x 520
    const int nC28  = (DIMC + BKK - 1) / BKK;        // 1
    const int nC300 = (HC   + BKK - 1) / BKK;        // 10

    concat_kernel<<<(NTOT * DIMC + 255) / 256, 256>>>(XY, V);
    init_acc_kernel<<<1, 1024>>>();

    // dn MLP
    mma_gemm_kernel<<<gH, blk>>>(in0,  dnW[0], dnb[0], bufA, nullptr, DIMC, HC, nC28,  1);
    mma_gemm_kernel<<<gH, blk>>>(bufA, dnW[1], dnb[1], bufB, nullptr, HC,   HC, nC300, 1);
    mma_gemm_kernel<<<gH, blk>>>(bufB, dnW[2], dnb[2], bufA, nullptr, HC,   HC, nC300, 1);
    mma_gemm_kernel<<<gH, blk>>>(bufA, dnW[3], dnb[3], bufB, nullptr, HC,   HC, nC300, 1);
    mma_gemm_kernel<<<gH, blk>>>(bufB, dnW[4], dnb[4], bufA, nullptr, HC,   HC, nC300, 1);
    mma_gemm_kernel<<<gF, blk>>>(bufA, dnW[5], dnb[5], F,    nullptr, HC,   FD, nC300, 0);

    // an MLP (residual on last layer)
    mma_gemm_kernel<<<gH, blk>>>(in0,  anW[0], anb[0], bufA, nullptr, DIMC, HC, nC28,  1);
    mma_gemm_kernel<<<gH, blk>>>(bufA, anW[1], anb[1], bufB, nullptr, HC,   HC, nC300, 1);
    mma_gemm_kernel<<<gH, blk>>>(bufB, anW[2], anb[2], bufA, nullptr, HC,   HC, nC300, 1);
    mma_gemm_kernel<<<gH, blk>>>(bufA, anW[3], anb[3], bufB, nullptr, HC,   HC, nC300, 1);
    mma_gemm_kernel<<<gH, blk>>>(bufB, anW[4], anb[4], bufA, nullptr, HC,   HC, nC300, 1);
    mma_gemm_kernel<<<gG, blk>>>(bufA, anW[5], anb[5], G,    in0,     HC,   GD, nC300, 0);

    // row norms
    row_norms_kernel<<<NTOT / 8, 256>>>(F, nF, FD, NTOT);
    row_norms_kernel<<<NTOT / 8, 256>>>(G, nG, GD, NTOT);

    // fm + partial reductions
    cudaFuncSetAttribute(fm_kernel, cudaFuncAttributeMaxDynamicSharedMemorySize,
                         FM_SMEM_FLOATS * (int)sizeof(float));
    fm_kernel<<<dim3(JC / 128, NXC / 32), 128, FM_SMEM_FLOATS * sizeof(float)>>>(
        eps, sig, sig0, cstp);

    // mu, s^2, final scalar
    mu_kernel<<<1, JC>>>();
    s2_kernel<<<NXC / 8, 256>>>();
    finalize_kernel<<<1, 1>>>((float*)d_out);
}

// round 4
// speedup vs baseline: 1.7535x; 1.0143x over previous
#include <cuda_runtime.h>
#include <cuda_bf16.h>
#include <math.h>
#include <stdint.h>

// Problem constants (fixed by the dataset)
#define NXC   32768
#define NTOT  66560          // 2*NX + J rows through both MLPs
#define DIMC  28
#define HC    300
#define FD    100            // dn output dim
#define GD    28             // an output dim
#define JC    1024

#define PWH   320            // padded hidden width (k and n padded)
#define WOFF  (320 * 320)    // per-layer packed weight size

// ---------------- scratch (static __device__ — no allocs allowed) ----------
__device__ float g_in0 [(size_t)NTOT * DIMC];                 // float input (residual)
__device__ __align__(16) __nv_bfloat16 g_inh[(size_t)NTOT * 32];
__device__ __align__(16) __nv_bfloat16 g_inl[(size_t)NTOT * 32];
__device__ __align__(16) __nv_bfloat16 g_Ah0[(size_t)NTOT * PWH];
__device__ __align__(16) __nv_bfloat16 g_Al0[(size_t)NTOT * PWH];
__device__ __align__(16) __nv_bfloat16 g_Ah1[(size_t)NTOT * PWH];
__device__ __align__(16) __nv_bfloat16 g_Al1[(size_t)NTOT * PWH];
__device__ __align__(16) __nv_bfloat16 g_Wh[12 * WOFF];
__device__ __align__(16) __nv_bfloat16 g_Wl[12 * WOFF];
__device__ float g_F   [(size_t)NTOT * FD];
__device__ float g_G   [(size_t)NTOT * GD];
__device__ float g_nF  [NTOT];
__device__ float g_nG  [NTOT];
__device__ float g_fm  [(size_t)NXC * JC];
__device__ float g_colsum[JC];
__device__ float g_mu    [JC];
__device__ float g_scal  [8];   // [0]=sum(fm^2) [1]=sum(s_i^2) [2]=sum(mu^2)

__device__ __forceinline__ void split2(float x, __nv_bfloat16& h, __nv_bfloat16& l) {
    h = __float2bfloat16(x);
    l = __float2bfloat16(x - __bfloat162float(h));
}

// ---------------- concat + input split -------------------------------------
__global__ void concat_kernel(const float* __restrict__ XY, const float* __restrict__ V) {
    int t = blockIdx.x * blockDim.x + threadIdx.x;
    const int total = NTOT * DIMC;
    const int xyn   = 2 * NXC * DIMC;
    if (t >= total) return;
    g_in0[t] = (t < xyn) ? XY[t] : V[t - xyn];
}
__global__ void concat_split_kernel(const float* __restrict__ XY, const float* __restrict__ V) {
    int t = blockIdx.x * blockDim.x + threadIdx.x;
    if (t >= NTOT * 32) return;
    int r = t >> 5, c = t & 31;
    float v = 0.0f;
    if (c < DIMC) {
        int idx = r * DIMC + c;
        v = (r < 2 * NXC) ? XY[idx] : V[(r - 2 * NXC) * DIMC + c];
    }
    __nv_bfloat16 h, l; split2(v, h, l);
    g_inh[t] = h; g_inl[t] = l;
}
// zero the k-pad columns (300..319) of the ping-pong activation buffers
__global__ void pad_zero_kernel() {
    int t = blockIdx.x * blockDim.x + threadIdx.x;
    if (t >= NTOT * (PWH - HC)) return;
    int r = t / (PWH - HC), c = HC + t % (PWH - HC);
    size_t o = (size_t)r * PWH + c;
    __nv_bfloat16 z = __float2bfloat16(0.0f);
    g_Ah0[o] = z; g_Al0[o] = z; g_Ah1[o] = z; g_Al1[o] = z;
}
__global__ void init_acc_kernel() {
    int t = threadIdx.x;
    if (t < JC) g_colsum[t] = 0.0f;
    if (t < 8)  g_scal[t]   = 0.0f;
}
// split one weight matrix into padded [320x320] hi/lo at layer offset
__global__ void prep_w_kernel(const float* __restrict__ W, int Fi, int Fo, int layer) {
    int idx = blockIdx.x * blockDim.x + threadIdx.x;
    if (idx >= WOFF) return;
    int k = idx / 320, n = idx - k * 320;
    float v = (k < Fi && n < Fo) ? W[(size_t)k * Fo + n] : 0.0f;
    __nv_bfloat16 h, l; split2(v, h, l);
    g_Wh[(size_t)layer * WOFF + idx] = h;
    g_Wl[(size_t)layer * WOFF + idx] = l;
}

// =============== bf16-split GEMM, pre-split operands, 3 passes ==============
#define BMM 128
#define BNN 64
#define BKK 32
#define A_STRIDE 40     // 32 + 8 pad (bf16)
#define B_STRIDE 72     // 64 + 8 pad (bf16)
// dynamic smem layout (bf16 elems): sAh[2][5120] sAl[2][5120] sBh[2][2304] sBl[2][2304]
#define SM_AH 0
#define SM_AL 10240
#define SM_BH 20480
#define SM_BL 25088
#define GEMM_SMEM_BYTES (29696 * 2)

__device__ __forceinline__ uint32_t smem_u32(const void* p) {
    uint32_t a;
    asm("{ .reg .u64 t; cvta.to.shared.u64 t, %1; cvt.u32.u64 %0, t; }" : "=r"(a) : "l"(p));
    return a;
}
__device__ __forceinline__ void ldsm_x4(uint32_t addr, uint32_t r[4]) {
    asm volatile("ldmatrix.sync.aligned.m8n8.x4.shared.b16 {%0,%1,%2,%3}, [%4];"
        : "=r"(r[0]), "=r"(r[1]), "=r"(r[2]), "=r"(r[3]) : "r"(addr));
}
__device__ __forceinline__ void ldsm_x4_t(uint32_t addr, uint32_t r[4]) {
    asm volatile("ldmatrix.sync.aligned.m8n8.x4.trans.shared.b16 {%0,%1,%2,%3}, [%4];"
        : "=r"(r[0]), "=r"(r[1]), "=r"(r[2]), "=r"(r[3]) : "r"(addr));
}
__device__ __forceinline__ void mma_bf16(float c[4], const uint32_t a[4],
                                         uint32_t b0, uint32_t b1) {
    asm volatile(
        "mma.sync.aligned.m16n8k16.row.col.f32.bf16.bf16.f32 "
        "{%0,%1,%2,%3}, {%4,%5,%6,%7}, {%8,%9}, {%0,%1,%2,%3};"
        : "+f"(c[0]), "+f"(c[1]), "+f"(c[2]), "+f"(c[3])
        : "r"(a[0]), "r"(a[1]), "r"(a[2]), "r"(a[3]), "r"(b0), "r"(b1));
}

__global__ __launch_bounds__(256, 2)
void mma_gemm2(const __nv_bfloat16* __restrict__ Ah, const __nv_bfloat16* __restrict__ Al,
               int PWa,
               const __nv_bfloat16* __restrict__ Wh, const __nv_bfloat16* __restrict__ Wl,
               const float* __restrict__ bias, int Fo,
               __nv_bfloat16* __restrict__ Ch, __nv_bfloat16* __restrict__ Cl,
               float* __restrict__ Cf, const float* __restrict__ res,
               int nC, int doRelu)
{
    extern __shared__ __nv_bfloat16 dyn[];

    const int tid    = threadIdx.x;
    const int lane   = tid & 31;
    const int wid    = tid >> 5;
    const int warp_m = wid >> 1;
    const int warp_n = wid & 1;
    const int rbase  = blockIdx.y * BMM;
    const int n0     = blockIdx.x * BNN;

    // global-load lane mapping
    const int a_row0 = tid >> 2;            // 0..63 (+64)
    const int a_kk   = (tid & 3) * 8;
    const int bk     = tid >> 3;            // 0..31
    const int bn     = (tid & 7) * 8;

    // ldmatrix lane mapping (within-buffer offsets, buf offset added per use)
    const uint32_t dyn32 = smem_u32(dyn);
    const int a_row  = warp_m * 32 + (lane & 15);
    const int a_kadd = (lane >> 4) * 8;
    const uint32_t aHiB = dyn32 + (uint32_t)(SM_AH + a_row * A_STRIDE + a_kadd) * 2u;
    const uint32_t aLoB = dyn32 + (uint32_t)(SM_AL + a_row * A_STRIDE + a_kadd) * 2u;
    const int b_k = (lane & 7) + ((lane & 8) ? 8 : 0);
    const int b_n = warp_n * 32 + ((lane & 16) ? 8 : 0);
    const uint32_t bHiB = dyn32 + (uint32_t)(SM_BH + b_k * B_STRIDE + b_n) * 2u;
    const uint32_t bLoB = dyn32 + (uint32_t)(SM_BL + b_k * B_STRIDE + b_n) * 2u;

    float acc[2][4][4];
    #pragma unroll
    for (int i = 0; i < 2; i++)
        #pragma unroll
        for (int j = 0; j < 4; j++)
            #pragma unroll
            for (int q = 0; q < 4; q++) acc[i][j][q] = 0.0f;

    uint4 pAh[2], pAl[2], pBh, pBl;

    // prologue: load + store chunk 0 into buffer 0
    {
        #pragma unroll
        for (int i = 0; i < 2; i++) {
            size_t off = (size_t)(rbase + a_row0 + 64 * i) * PWa + a_kk;
            pAh[i] = *(const uint4*)(Ah + off);
            pAl[i] = *(const uint4*)(Al + off);
        }
        size_t boff = (size_t)bk * 320 + n0 + bn;
        pBh = *(const uint4*)(Wh + boff);
        pBl = *(const uint4*)(Wl + boff);
        #pragma unroll
        for (int i = 0; i < 2; i++) {
            int so = (a_row0 + 64 * i) * A_STRIDE + a_kk;
            *(uint4*)(dyn + SM_AH + so) = pAh[i];
            *(uint4*)(dyn + SM_AL + so) = pAl[i];
        }
        int sb = bk * B_STRIDE + bn;
        *(uint4*)(dyn + SM_BH + sb) = pBh;
        *(uint4*)(dyn + SM_BL + sb) = pBl;
    }
    __syncthreads();

    for (int c = 0; c < nC; c++) {
        const int buf = c & 1;
        const uint32_t aOff = (uint32_t)(buf * 5120 * 2);
        const uint32_t bOff = (uint32_t)(buf * 2304 * 2);

        // prefetch chunk c+1 into registers (overlaps MMA)
        if (c + 1 < nC) {
            const int k0 = (c + 1) * BKK;
            #pragma unroll
            for (int i = 0; i < 2; i++) {
                size_t off = (size_t)(rbase + a_row0 + 64 * i) * PWa + k0 + a_kk;
                pAh[i] = *(const uint4*)(Ah + off);
                pAl[i] = *(const uint4*)(Al + off);
            }
            size_t boff = (size_t)(k0 + bk) * 320 + n0 + bn;
            pBh = *(const uint4*)(Wh + boff);
            pBl = *(const uint4*)(Wl + boff);
        }

        // MMA over this chunk: 2 ksteps of 16, 3 passes each
        #pragma unroll
        for (int ks = 0; ks < 2; ks++) {
            uint32_t Ahr[2][4], Alr[2][4], Bhr[2][4], Blr[2][4];
            #pragma unroll
            for (int mi = 0; mi < 2; mi++) {
                uint32_t off = aOff + (uint32_t)(mi * 16 * A_STRIDE + ks * 16) * 2u;
                ldsm_x4(aHiB + off, Ahr[mi]);
                ldsm_x4(aLoB + off, Alr[mi]);
            }
            #pragma unroll
            for (int np = 0; np < 2; np++) {
                uint32_t off = bOff + (uint32_t)(np * 16 + ks * 16 * B_STRIDE) * 2u;
                ldsm_x4_t(bHiB + off, Bhr[np]);
                ldsm_x4_t(bLoB + off, Blr[np]);
            }
            #pragma unroll
            for (int mi = 0; mi < 2; mi++)
                #pragma unroll
                for (int nj = 0; nj < 4; nj++) {
                    const int np = nj >> 1, hf = (nj & 1) * 2;
                    mma_bf16(acc[mi][nj], Ahr[mi], Bhr[np][hf], Bhr[np][hf + 1]);
                    mma_bf16(acc[mi][nj], Ahr[mi], Blr[np][hf], Blr[np][hf + 1]);
                    mma_bf16(acc[mi][nj], Alr[mi], Bhr[np][hf], Bhr[np][hf + 1]);
                }
        }

        // store prefetched chunk into other buffer, then single sync
        if (c + 1 < nC) {
            const int ob = (c + 1) & 1;
            #pragma unroll
            for (int i = 0; i < 2; i++) {
                int so = ob * 5120 + (a_row0 + 64 * i) * A_STRIDE + a_kk;
                *(uint4*)(dyn + SM_AH + so) = pAh[i];
                *(uint4*)(dyn + SM_AL + so) = pAl[i];
            }
            int sb = ob * 2304 + bk * B_STRIDE + bn;
            *(uint4*)(dyn + SM_BH + sb) = pBh;
            *(uint4*)(dyn + SM_BL + sb) = pBl;
            __syncthreads();
        }
    }

    // epilogue
    #pragma unroll
    for (int mi = 0; mi < 2; mi++)
        #pragma unroll
        for (int nj = 0; nj < 4; nj++) {
            int col = n0 + warp_n * 32 + nj * 8 + (lane & 3) * 2;
            if (col >= Fo) continue;
            float2 b2 = *(const float2*)(bias + col);
            #pragma unroll
            for (int half = 0; half < 2; half++) {
                int row = rbase + warp_m * 32 + mi * 16 + (lane >> 2) + half * 8;
                float vx = acc[mi][nj][half * 2 + 0] + b2.x;
                float vy = acc[mi][nj][half * 2 + 1] + b2.y;
                if (res) {
                    float2 r2 = *(const float2*)(res + (size_t)row * Fo + col);
                    vx += r2.x; vy += r2.y;
                }
                if (doRelu) { vx = fmaxf(vx, 0.0f); vy = fmaxf(vy, 0.0f); }
                if (Cf) {
                    *(float2*)(Cf + (size_t)row * Fo + col) = make_float2(vx, vy);
                } else {
                    __nv_bfloat16 hx, lx, hy, ly;
                    split2(vx, hx, lx); split2(vy, hy, ly);
                    *(__nv_bfloat162*)(Ch + (size_t)row * PWH + col) = __halves2bfloat162(hx, hy);
                    *(__nv_bfloat162*)(Cl + (size_t)row * PWH + col) = __halves2bfloat162(lx, ly);
                }
            }
        }
}

// ---------------- row squared norms ----------------------------------------
__global__ void row_norms_kernel(const float* __restrict__ X, float* __restrict__ out,
                                 int D, int n)
{
    int warp = (blockIdx.x * blockDim.x + threadIdx.x) >> 5;
    int lane = threadIdx.x & 31;
    if (warp >= n) return;
    float s = 0.0f;
    for (int k = lane; k < D; k += 32) {
        float v = X[(size_t)warp * D + k];
        s += v * v;
    }
    #pragma unroll
    for (int o = 16; o; o >>= 1) s += __shfl_xor_sync(0xffffffffu, s, o);
    if (lane == 0) out[warp] = s;
}

// ---------------- fm kernel: 32 i-rows x 128 j-cols per block --------------
#define FM_SMEM_FLOATS 25088

__global__ __launch_bounds__(128)
void fm_kernel(const float* __restrict__ eps_p, const float* __restrict__ sig_p,
               const float* __restrict__ sig0_p, const float* __restrict__ cst_p)
{
    extern __shared__ float sm[];
    float* sFV = sm;             // 12800
    float* sGV = sm + 12800;     // 3584
    float* sFX = sm + 16384;     // 3200
    float* sFY = sm + 19584;     // 3200
    float* sGX = sm + 22784;     // 896
    float* sGY = sm + 23680;     // 896
    float* nfv = sm + 24576;     // 128
    float* ngv = sm + 24704;     // 128
    float* nfx = sm + 24832;     // 32
    float* nfy = sm + 24864;     // 32
    float* ngx = sm + 24896;     // 32
    float* ngy = sm + 24928;     // 32
    float* red = sm + 24960;     // 128

    const int tid   = threadIdx.x;
    const int jbase = blockIdx.x * 128;
    const int ibase = blockIdx.y * 32;
    const int YOFF  = NXC;
    const int VOFF  = 2 * NXC;

    for (int e = tid; e < 128 * FD; e += 128) {
        int r = e / FD, k = e - r * FD;
        sFV[k * 128 + r] = g_F[(size_t)(VOFF + jbase + r) * FD + k];
    }
    for (int e = tid; e < 128 * GD; e += 128) {
        int r = e / GD, k = e - r * GD;
        sGV[k * 128 + r] = g_G[(size_t)(VOFF + jbase + r) * GD + k];
    }
    for (int e = tid; e < 32 * FD; e += 128) {
        int r = e / FD, k = e - r * FD;
        sFX[k * 32 + r] = g_F[(size_t)(ibase + r) * FD + k];
        sFY[k * 32 + r] = g_F[(size_t)(YOFF + ibase + r) * FD + k];
    }
    for (int e = tid; e < 32 * GD; e += 128) {
        int r = e / GD, k = e - r * GD;
        sGX[k * 32 + r] = g_G[(size_t)(ibase + r) * GD + k];
        sGY[k * 32 + r] = g_G[(size_t)(YOFF + ibase + r) * GD + k];
    }
    if (tid < 128) { nfv[tid] = g_nF[VOFF + jbase + tid]; ngv[tid] = g_nG[VOFF + jbase + tid]; }
    if (tid < 32)  {
        nfx[tid] = g_nF[ibase + tid];        nfy[tid] = g_nF[YOFF + ibase + tid];
        ngx[tid] = g_nG[ibase + tid];        ngy[tid] = g_nG[YOFF + ibase + tid];
    }
    __syncthreads();

    const float ep     = 1.0f / (1.0f + __expf(-eps_p[0]));
    const float inv_s  = 1.0f / (sig_p[0]  * sig_p[0]);
    const float inv_s0 = 1.0f / (sig0_p[0] * sig0_p[0]);
    const float cstv   = cst_p[0];
    const float one_ep = 1.0f - ep;
    const float RS     = 0.03125f;   // 1/sqrt(1024)

    const int ti = tid >> 4;
    const int tj = tid & 15;
    const int i0 = ti * 4;
    const int j0 = tj * 8;

    float dx[4][8], dy[4][8];
    #pragma unroll
    for (int a = 0; a < 4; a++)
        #pragma unroll
        for (int b = 0; b < 8; b++) { dx[a][b] = 0.0f; dy[a][b] = 0.0f; }

    #pragma unroll 2
    for (int k = 0; k < FD; k++) {
        float4 a4  = *(const float4*)(sFX + k * 32  + i0);
        float4 c4  = *(const float4*)(sFY + k * 32  + i0);
        float4 b40 = *(const float4*)(sFV + k * 128 + j0);
        float4 b41 = *(const float4*)(sFV + k * 128 + j0 + 4);
        float av[4] = {a4.x, a4.y, a4.z, a4.w};
        float cv[4] = {c4.x, c4.y, c4.z, c4.w};
        float bv[8] = {b40.x, b40.y, b40.z, b40.w, b41.x, b41.y, b41.z, b41.w};
        #pragma unroll
        for (int ii = 0; ii < 4; ii++)
            #pragma unroll
            for (int jj = 0; jj < 8; jj++) {
                dx[ii][jj] += av[ii] * bv[jj];
                dy[ii][jj] += cv[ii] * bv[jj];
            }
    }
    #pragma unroll
    for (int ii = 0; ii < 4; ii++)
        #pragma unroll
        for (int jj = 0; jj < 8; jj++) {
            float Dx = fmaxf(nfx[i0 + ii] + nfv[j0 + jj] - 2.0f * dx[ii][jj], 0.0f);
            float Dy = fmaxf(nfy[i0 + ii] + nfv[j0 + jj] - 2.0f * dy[ii][jj], 0.0f);
            dx[ii][jj] = one_ep * __expf(-Dx * inv_s0) + ep;
            dy[ii][jj] = one_ep * __expf(-Dy * inv_s0) + ep;
        }

    float gx[4][8], gy[4][8];
    #pragma unroll
    for (int a = 0; a < 4; a++)
        #pragma unroll
        for (int b = 0; b < 8; b++) { gx[a][b] = 0.0f; gy[a][b] = 0.0f; }

    #pragma unroll
    for (int k = 0; k < GD; k++) {
        float4 a4  = *(const float4*)(sGX + k * 32  + i0);
        float4 c4  = *(const float4*)(sGY + k * 32  + i0);
        float4 b40 = *(const float4*)(sGV + k * 128 + j0);
        float4 b41 = *(const float4*)(sGV + k * 128 + j0 + 4);
        float av[4] = {a4.x, a4.y, a4.z, a4.w};
        float cv[4] = {c4.x, c4.y, c4.z, c4.w};
        float bv[8] = {b40.x, b40.y, b40.z, b40.w, b41.x, b41.y, b41.z, b41.w};
        #pragma unroll
        for (int ii = 0; ii < 4; ii++)
            #pragma unroll
            for (int jj = 0; jj < 8; jj++) {
                gx[ii][jj] += av[ii] * bv[jj];
                gy[ii][jj] += cv[ii] * bv[jj];
            }
    }

    float csum[8];
    #pragma unroll
    for (int jj = 0; jj < 8; jj++) csum[jj] = 0.0f;
    float q = 0.0f;

    #pragma unroll
    for (int ii = 0; ii < 4; ii++) {
        float vout[8];
        #pragma unroll
        for (int jj = 0; jj < 8; jj++) {
            float Dgx = fmaxf(ngx[i0 + ii] + ngv[j0 + jj] - 2.0f * gx[ii][jj], 0.0f);
            float Dgy = fmaxf(ngy[i0 + ii] + ngv[j0 + jj] - 2.0f * gy[ii][jj], 0.0f);
            float KX  = cstv * dx[ii][jj] * __expf(-Dgx * inv_s);
            float KY  = cstv * dy[ii][jj] * __expf(-Dgy * inv_s);
            float v   = (KX - KY) * RS;
            vout[jj] = v;
            csum[jj] += v;
            q += v * v;
        }
        size_t basei = (size_t)(ibase + i0 + ii) * JC + jbase + j0;
        *(float4*)(g_fm + basei)     = make_float4(vout[0], vout[1], vout[2], vout[3]);
        *(float4*)(g_fm + basei + 4) = make_float4(vout[4], vout[5], vout[6], vout[7]);
    }
    #pragma unroll
    for (int jj = 0; jj < 8; jj++)
        atomicAdd(&g_colsum[jbase + j0 + jj], csum[jj]);

    red[tid] = q;
    __syncthreads();
    for (int s = 64; s; s >>= 1) {
        if (tid < s) red[tid] += red[tid + s];
        __syncthreads();
    }
    if (tid == 0) atomicAdd(&g_scal[0], red[0]);
}

// ---------------- mu + sum(mu^2) --------------------------------------------
__global__ void mu_kernel() {
    __shared__ float red[JC];
    int j = threadIdx.x;
    float m = g_colsum[j] * (1.0f / (float)NXC);
    g_mu[j] = m;
    red[j] = m * m;
    __syncthreads();
    for (int s = 512; s; s >>= 1) {
        if (j < s) red[j] += red[j + s];
        __syncthreads();
    }
    if (j == 0) g_scal[2] = red[0];
}

// ---------------- s_i = fm[i]·mu ; accumulate s_i^2 -------------------------
__global__ __launch_bounds__(256) void s2_kernel() {
    __shared__ float smu[JC];
    int tid = threadIdx.x;
    for (int e = tid; e < JC; e += 256) smu[e] = g_mu[e];
    __syncthreads();
    int row  = blockIdx.x * 8 + (tid >> 5);
    int lane = tid & 31;
    float s = 0.0f;
    #pragma unroll 4
    for (int t = 0; t < 32; t++) {
        int c = lane + 32 * t;
        s += g_fm[(size_t)row * JC + c] * smu[c];
    }
    #pragma unroll
    for (int o = 16; o; o >>= 1) s += __shfl_xor_sync(0xffffffffu, s, o);
    if (lane == 0) atomicAdd(&g_scal[1], s * s);
}

// ---------------- finalize (fp64 to kill cancellation) ----------------------
__global__ void finalize_kernel(float* out) {
    double sumfm2 = (double)g_scal[0];
    double sums2  = (double)g_scal[1];
    double summu2 = (double)g_scal[2];
    double nx = (double)NXC;
    double t1 = summu2 * (nx / (nx - 1.0));
    double t2 = sumfm2 / nx / (nx - 1.0);
    double mean = t1 - t2;
    double var  = 4.0 * (sums2 / nx) - 4.0 * summu2 * summu2;
    out[0] = (float)(-(mean / sqrt(var + 1e-6)));
}

// ---------------- launch -----------------------------------------------------
extern "C" void kernel_launch(void* const* d_in, const int* in_sizes, int n_in,
                              void* d_out, int out_size)
{
    const float* XY = (const float*)d_in[0];
    const float* V  = (const float*)d_in[1];
    const float *dnW[6], *dnb[6], *anW[6], *anb[6];
    for (int i = 0; i < 6; i++) {
        dnW[i] = (const float*)d_in[2 + 2 * i];
        dnb[i] = (const float*)d_in[3 + 2 * i];
        anW[i] = (const float*)d_in[14 + 2 * i];
        anb[i] = (const float*)d_in[15 + 2 * i];
    }
    const float* eps   = (const float*)d_in[26];
    const float* sig   = (const float*)d_in[27];
    const float* sig0  = (const float*)d_in[28];
    const float* cstp  = (const float*)d_in[29];

    float *in0, *F, *G, *nF, *nG;
    __nv_bfloat16 *inh, *inl, *h0, *l0, *h1, *l1, *Wh, *Wl;
    cudaGetSymbolAddress((void**)&in0, g_in0);
    cudaGetSymbolAddress((void**)&F,   g_F);
    cudaGetSymbolAddress((void**)&G,   g_G);
    cudaGetSymbolAddress((void**)&nF,  g_nF);
    cudaGetSymbolAddress((void**)&nG,  g_nG);
    cudaGetSymbolAddress((void**)&inh, g_inh);
    cudaGetSymbolAddress((void**)&inl, g_inl);
    cudaGetSymbolAddress((void**)&h0,  g_Ah0);
    cudaGetSymbolAddress((void**)&l0,  g_Al0);
    cudaGetSymbolAddress((void**)&h1,  g_Ah1);
    cudaGetSymbolAddress((void**)&l1,  g_Al1);
    cudaGetSymbolAddress((void**)&Wh,  g_Wh);
    cudaGetSymbolAddress((void**)&Wl,  g_Wl);

    const int GY = NTOT / BMM;                       // 520
    const dim3 blk(256);
    const dim3 gH((HC + BNN - 1) / BNN, GY);         // 5 x 520
    const dim3 gF((FD + BNN - 1) / BNN, GY);         // 2 x 520
    const dim3 gG((GD + BNN - 1) / BNN, GY);         // 1 x 520
    const int nC28  = 1;
    const int nC300 = 10;

    concat_kernel<<<(NTOT * DIMC + 255) / 256, 256>>>(XY, V);
    concat_split_kernel<<<(NTOT * 32 + 255) / 256, 256>>>(XY, V);
    pad_zero_kernel<<<(NTOT * (PWH - HC) + 255) / 256, 256>>>();
    init_acc_kernel<<<1, 1024>>>();

    // weight prep (padded 320x320 hi/lo per layer; dn = layers 0..5, an = 6..11)
    prep_w_kernel<<<(WOFF + 255) / 256, 256>>>(dnW[0], DIMC, HC, 0);
    prep_w_kernel<<<(WOFF + 255) / 256, 256>>>(dnW[1], HC,   HC, 1);
    prep_w_kernel<<<(WOFF + 255) / 256, 256>>>(dnW[2], HC,   HC, 2);
    prep_w_kernel<<<(WOFF + 255) / 256, 256>>>(dnW[3], HC,   HC, 3);
    prep_w_kernel<<<(WOFF + 255) / 256, 256>>>(dnW[4], HC,   HC, 4);
    prep_w_kernel<<<(WOFF + 255) / 256, 256>>>(dnW[5], HC,   FD, 5);
    prep_w_kernel<<<(WOFF + 255) / 256, 256>>>(anW[0], DIMC, HC, 6);
    prep_w_kernel<<<(WOFF + 255) / 256, 256>>>(anW[1], HC,   HC, 7);
    prep_w_kernel<<<(WOFF + 255) / 256, 256>>>(anW[2], HC,   HC, 8);
    prep_w_kernel<<<(WOFF + 255) / 256, 256>>>(anW[3], HC,   HC, 9);
    prep_w_kernel<<<(WOFF + 255) / 256, 256>>>(anW[4], HC,   HC, 10);
    prep_w_kernel<<<(WOFF + 255) / 256, 256>>>(anW[5], HC,   GD, 11);

    cudaFuncSetAttribute(mma_gemm2, cudaFuncAttributeMaxDynamicSharedMemorySize,
                         GEMM_SMEM_BYTES);
    #define GEMM(grid, Ahp, Alp, PWa, L, bias, Fo, Chp, Clp, Cfp, resp, nC, relu) \
        mma_gemm2<<<grid, blk, GEMM_SMEM_BYTES>>>(Ahp, Alp, PWa, \
            Wh + (size_t)(L) * WOFF, Wl + (size_t)(L) * WOFF, bias, Fo, \
            Chp, Clp, Cfp, resp, nC, relu)

    // dn MLP
    GEMM(gH, inh, inl, 32,  0, dnb[0], HC, h0, l0, (float*)0, (const float*)0, nC28,  1);
    GEMM(gH, h0,  l0,  PWH, 1, dnb[1], HC, h1, l1, (float*)0, (const float*)0, nC300, 1);
    GEMM(gH, h1,  l1,  PWH, 2, dnb[2], HC, h0, l0, (float*)0, (const float*)0, nC300, 1);
    GEMM(gH, h0,  l0,  PWH, 3, dnb[3], HC, h1, l1, (float*)0, (const float*)0, nC300, 1);
    GEMM(gH, h1,  l1,  PWH, 4, dnb[4], HC, h0, l0, (float*)0, (const float*)0, nC300, 1);
    GEMM(gF, h0,  l0,  PWH, 5, dnb[5], FD, (__nv_bfloat16*)0, (__nv_bfloat16*)0, F, (const float*)0, nC300, 0);

    // an MLP (residual on last layer)
    GEMM(gH, inh, inl, 32,  6, anb[0], HC, h1, l1, (float*)0, (const float*)0, nC28,  1);
    GEMM(gH, h1,  l1,  PWH, 7, anb[1], HC, h0, l0, (float*)0, (const float*)0, nC300, 1);
    GEMM(gH, h0,  l0,  PWH, 8, anb[2], HC, h1, l1, (float*)0, (const float*)0, nC300, 1);
    GEMM(gH, h1,  l1,  PWH, 9, anb[3], HC, h0, l0, (float*)0, (const float*)0, nC300, 1);
    GEMM(gH, h0,  l0,  PWH, 10, anb[4], HC, h1, l1, (float*)0, (const float*)0, nC300, 1);
    GEMM(gG, h1,  l1,  PWH, 11, anb[5], GD, (__nv_bfloat16*)0, (__nv_bfloat16*)0, G, in0, nC300, 0);

    // row norms
    row_norms_kernel<<<NTOT / 8, 256>>>(F, nF, FD, NTOT);
    row_norms_kernel<<<NTOT / 8, 256>>>(G, nG, GD, NTOT);

    // fm + partial reductions
    cudaFuncSetAttribute(fm_kernel, cudaFuncAttributeMaxDynamicSharedMemorySize,
                         FM_SMEM_FLOATS * (int)sizeof(float));
    fm_kernel<<<dim3(JC / 128, NXC / 32), 128, FM_SMEM_FLOATS * sizeof(float)>>>(
        eps, sig, sig0, cstp);

    // mu, s^2, final scalar
    mu_kernel<<<1, JC>>>();
    s2_kernel<<<NXC / 8, 256>>>();
    finalize_kernel<<<1, 1>>>((float*)d_out);
}

// round 5
// speedup vs baseline: 2.1064x; 1.2012x over previous
#include <cuda_runtime.h>
#include <cuda_bf16.h>
#include <math.h>
#include <stdint.h>

// Problem constants (fixed by the dataset)
#define NXC   32768
#define NTOT  66560          // 2*NX + J rows through both MLPs
#define DIMC  28
#define HC    300
#define FD    100            // dn output dim
#define GD    28             // an output dim
#define JC    1024

#define PWH   320            // padded hidden width
#define FDP   112            // padded F width (k16 multiple)
#define GDP   32             // padded G width
#define WOFF  (320 * 320)

// ---------------- scratch (static __device__ — no allocs allowed) ----------
__device__ float g_in0 [(size_t)NTOT * DIMC];
__device__ __align__(16) __nv_bfloat16 g_inh[(size_t)NTOT * 32];
__device__ __align__(16) __nv_bfloat16 g_inl[(size_t)NTOT * 32];
__device__ __align__(16) __nv_bfloat16 g_Ah0[(size_t)NTOT * PWH];
__device__ __align__(16) __nv_bfloat16 g_Al0[(size_t)NTOT * PWH];
__device__ __align__(16) __nv_bfloat16 g_Ah1[(size_t)NTOT * PWH];
__device__ __align__(16) __nv_bfloat16 g_Al1[(size_t)NTOT * PWH];
__device__ __align__(16) __nv_bfloat16 g_Wh[12 * WOFF];
__device__ __align__(16) __nv_bfloat16 g_Wl[12 * WOFF];
__device__ __align__(16) __nv_bfloat16 g_Fh[(size_t)NTOT * FDP];
__device__ __align__(16) __nv_bfloat16 g_Fl[(size_t)NTOT * FDP];
__device__ __align__(16) __nv_bfloat16 g_Gh[(size_t)NTOT * GDP];
__device__ __align__(16) __nv_bfloat16 g_Gl[(size_t)NTOT * GDP];
__device__ float g_nF  [NTOT];
__device__ float g_nG  [NTOT];
__device__ float g_fm  [(size_t)NXC * JC];
__device__ float g_colsum[JC];
__device__ float g_mu    [JC];
__device__ float g_scal  [8];   // [0]=sum(fm^2) [1]=sum(s_i^2) [2]=sum(mu^2)

__device__ __forceinline__ void split2(float x, __nv_bfloat16& h, __nv_bfloat16& l) {
    h = __float2bfloat16(x);
    l = __float2bfloat16(x - __bfloat162float(h));
}

// Fast exp on the FMA/ALU pipes (x <= 0 expected; abs err ~2e-7).
__device__ __forceinline__ float fexp(float x) {
    x = fmaxf(x, -80.0f);
    float w  = x * 1.4426950408889634f;           // log2(e)
    float kf = w + 12582912.0f;                   // rint via 1.5*2^23 magic
    int   n  = __float_as_int(kf) - 0x4B400000;
    float f  = w - (kf - 12582912.0f);            // in [-0.5, 0.5]
    float y  = f * 0.6931471805599453f;           // ln2
    float p  = 1.3888889e-3f;
    p = fmaf(p, y, 8.3333333e-3f);
    p = fmaf(p, y, 4.1666668e-2f);
    p = fmaf(p, y, 0.16666667f);
    p = fmaf(p, y, 0.5f);
    p = fmaf(p, y, 1.0f);
    p = fmaf(p, y, 1.0f);
    return p * __int_as_float((n + 127) << 23);
}

// ---------------- prep kernels ----------------------------------------------
__global__ void concat_kernel(const float* __restrict__ XY, const float* __restrict__ V) {
    int t = blockIdx.x * blockDim.x + threadIdx.x;
    const int total = NTOT * DIMC;
    const int xyn   = 2 * NXC * DIMC;
    if (t >= total) return;
    g_in0[t] = (t < xyn) ? XY[t] : V[t - xyn];
}
__global__ void concat_split_kernel(const float* __restrict__ XY, const float* __restrict__ V) {
    int t = blockIdx.x * blockDim.x + threadIdx.x;
    if (t >= NTOT * 32) return;
    int r = t >> 5, c = t & 31;
    float v = 0.0f;
    if (c < DIMC) {
        int idx = r * DIMC + c;
        v = (r < 2 * NXC) ? XY[idx] : V[(r - 2 * NXC) * DIMC + c];
    }
    __nv_bfloat16 h, l; split2(v, h, l);
    g_inh[t] = h; g_inl[t] = l;
}
__global__ void pad_zero_kernel() {   // activation k-pads (300..319)
    int t = blockIdx.x * blockDim.x + threadIdx.x;
    if (t >= NTOT * (PWH - HC)) return;
    int r = t / (PWH - HC), c = HC + t % (PWH - HC);
    size_t o = (size_t)r * PWH + c;
    __nv_bfloat16 z = __float2bfloat16(0.0f);
    g_Ah0[o] = z; g_Al0[o] = z; g_Ah1[o] = z; g_Al1[o] = z;
}
__global__ void pad_fg_kernel() {     // F pads (100..111), G pads (28..31)
    int t = blockIdx.x * blockDim.x + threadIdx.x;
    if (t >= NTOT * 12) return;
    int r = t / 12, c = t % 12;
    __nv_bfloat16 z = __float2bfloat16(0.0f);
    size_t of = (size_t)r * FDP + 100 + c;
    g_Fh[of] = z; g_Fl[of] = z;
    if (c < 4) {
        size_t og = (size_t)r * GDP + 28 + c;
        g_Gh[og] = z; g_Gl[og] = z;
    }
}
__global__ void init_acc_kernel() {
    int t = threadIdx.x;
    if (t < JC) g_colsum[t] = 0.0f;
    if (t < 8)  g_scal[t]   = 0.0f;
}
__global__ void prep_w_kernel(const float* __restrict__ W, int Fi, int Fo, int layer) {
    int idx = blockIdx.x * blockDim.x + threadIdx.x;
    if (idx >= WOFF) return;
    int k = idx / 320, n = idx - k * 320;
    float v = (k < Fi && n < Fo) ? W[(size_t)k * Fo + n] : 0.0f;
    __nv_bfloat16 h, l; split2(v, h, l);
    g_Wh[(size_t)layer * WOFF + idx] = h;
    g_Wl[(size_t)layer * WOFF + idx] = l;
}

// =============== shared MMA helpers ==========================================
__device__ __forceinline__ uint32_t smem_u32(const void* p) {
    uint32_t a;
    asm("{ .reg .u64 t; cvta.to.shared.u64 t, %1; cvt.u32.u64 %0, t; }" : "=r"(a) : "l"(p));
    return a;
}
__device__ __forceinline__ void ldsm_x4(uint32_t addr, uint32_t r[4]) {
    asm volatile("ldmatrix.sync.aligned.m8n8.x4.shared.b16 {%0,%1,%2,%3}, [%4];"
        : "=r"(r[0]), "=r"(r[1]), "=r"(r[2]), "=r"(r[3]) : "r"(addr));
}
__device__ __forceinline__ void ldsm_x4_t(uint32_t addr, uint32_t r[4]) {
    asm volatile("ldmatrix.sync.aligned.m8n8.x4.trans.shared.b16 {%0,%1,%2,%3}, [%4];"
        : "=r"(r[0]), "=r"(r[1]), "=r"(r[2]), "=r"(r[3]) : "r"(addr));
}
__device__ __forceinline__ void mma_bf16(float c[4], const uint32_t a[4],
                                         uint32_t b0, uint32_t b1) {
    asm volatile(
        "mma.sync.aligned.m16n8k16.row.col.f32.bf16.bf16.f32 "
        "{%0,%1,%2,%3}, {%4,%5,%6,%7}, {%8,%9}, {%0,%1,%2,%3};"
        : "+f"(c[0]), "+f"(c[1]), "+f"(c[2]), "+f"(c[3])
        : "r"(a[0]), "r"(a[1]), "r"(a[2]), "r"(a[3]), "r"(b0), "r"(b1));
}

// =============== bf16-split GEMM (unchanged mainloop from R4) ================
#define BMM 128
#define BNN 64
#define BKK 32
#define A_STRIDE 40
#define B_STRIDE 72
#define SM_AH 0
#define SM_AL 10240
#define SM_BH 20480
#define SM_BL 25088
#define GEMM_SMEM_BYTES (29696 * 2)

__global__ __launch_bounds__(256, 2)
void mma_gemm2(const __nv_bfloat16* __restrict__ Ah, const __nv_bfloat16* __restrict__ Al,
               int PWa,
               const __nv_bfloat16* __restrict__ Wh, const __nv_bfloat16* __restrict__ Wl,
               const float* __restrict__ bias, int Fo,
               __nv_bfloat16* __restrict__ Ch, __nv_bfloat16* __restrict__ Cl, int PWc,
               const float* __restrict__ res,
               int nC, int doRelu)
{
    extern __shared__ __nv_bfloat16 dyn[];

    const int tid    = threadIdx.x;
    const int lane   = tid & 31;
    const int wid    = tid >> 5;
    const int warp_m = wid >> 1;
    const int warp_n = wid & 1;
    const int rbase  = blockIdx.y * BMM;
    const int n0     = blockIdx.x * BNN;

    const int a_row0 = tid >> 2;
    const int a_kk   = (tid & 3) * 8;
    const int bk     = tid >> 3;
    const int bn     = (tid & 7) * 8;

    const uint32_t dyn32 = smem_u32(dyn);
    const int a_row  = warp_m * 32 + (lane & 15);
    const int a_kadd = (lane >> 4) * 8;
    const uint32_t aHiB = dyn32 + (uint32_t)(SM_AH + a_row * A_STRIDE + a_kadd) * 2u;
    const uint32_t aLoB = dyn32 + (uint32_t)(SM_AL + a_row * A_STRIDE + a_kadd) * 2u;
    const int b_k = (lane & 7) + ((lane & 8) ? 8 : 0);
    const int b_n = warp_n * 32 + ((lane & 16) ? 8 : 0);
    const uint32_t bHiB = dyn32 + (uint32_t)(SM_BH + b_k * B_STRIDE + b_n) * 2u;
    const uint32_t bLoB = dyn32 + (uint32_t)(SM_BL + b_k * B_STRIDE + b_n) * 2u;

    float acc[2][4][4];
    #pragma unroll
    for (int i = 0; i < 2; i++)
        #pragma unroll
        for (int j = 0; j < 4; j++)
            #pragma unroll
            for (int q = 0; q < 4; q++) acc[i][j][q] = 0.0f;

    uint4 pAh[2], pAl[2], pBh, pBl;

    {
        #pragma unroll
        for (int i = 0; i < 2; i++) {
            size_t off = (size_t)(rbase + a_row0 + 64 * i) * PWa + a_kk;
            pAh[i] = *(const uint4*)(Ah + off);
            pAl[i] = *(const uint4*)(Al + off);
        }
        size_t boff = (size_t)bk * 320 + n0 + bn;
        pBh = *(const uint4*)(Wh + boff);
        pBl = *(const uint4*)(Wl + boff);
        #pragma unroll
        for (int i = 0; i < 2; i++) {
            int so = (a_row0 + 64 * i) * A_STRIDE + a_kk;
            *(uint4*)(dyn + SM_AH + so) = pAh[i];
            *(uint4*)(dyn + SM_AL + so) = pAl[i];
        }
        int sb = bk * B_STRIDE + bn;
        *(uint4*)(dyn + SM_BH + sb) = pBh;
        *(uint4*)(dyn + SM_BL + sb) = pBl;
    }
    __syncthreads();

    for (int c = 0; c < nC; c++) {
        const int buf = c & 1;
        const uint32_t aOff = (uint32_t)(buf * 5120 * 2);
        const uint32_t bOff = (uint32_t)(buf * 2304 * 2);

        if (c + 1 < nC) {
            const int k0 = (c + 1) * BKK;
            #pragma unroll
            for (int i = 0; i < 2; i++) {
                size_t off = (size_t)(rbase + a_row0 + 64 * i) * PWa + k0 + a_kk;
                pAh[i] = *(const uint4*)(Ah + off);
                pAl[i] = *(const uint4*)(Al + off);
            }
            size_t boff = (size_t)(k0 + bk) * 320 + n0 + bn;
            pBh = *(const uint4*)(Wh + boff);
            pBl = *(const uint4*)(Wl + boff);
        }

        #pragma unroll
        for (int ks = 0; ks < 2; ks++) {
            uint32_t Ahr[2][4], Alr[2][4], Bhr[2][4], Blr[2][4];
            #pragma unroll
            for (int mi = 0; mi < 2; mi++) {
                uint32_t off = aOff + (uint32_t)(mi * 16 * A_STRIDE + ks * 16) * 2u;
                ldsm_x4(aHiB + off, Ahr[mi]);
                ldsm_x4(aLoB + off, Alr[mi]);
            }
            #pragma unroll
            for (int np = 0; np < 2; np++) {
                uint32_t off = bOff + (uint32_t)(np * 16 + ks * 16 * B_STRIDE) * 2u;
                ldsm_x4_t(bHiB + off, Bhr[np]);
                ldsm_x4_t(bLoB + off, Blr[np]);
            }
            #pragma unroll
            for (int mi = 0; mi < 2; mi++)
                #pragma unroll
                for (int nj = 0; nj < 4; nj++) {
                    const int np = nj >> 1, hf = (nj & 1) * 2;
                    mma_bf16(acc[mi][nj], Ahr[mi], Bhr[np][hf], Bhr[np][hf + 1]);
                    mma_bf16(acc[mi][nj], Ahr[mi], Blr[np][hf], Blr[np][hf + 1]);
                    mma_bf16(acc[mi][nj], Alr[mi], Bhr[np][hf], Bhr[np][hf + 1]);
                }
        }

        if (c + 1 < nC) {
            const int ob = (c + 1) & 1;
            #pragma unroll
            for (int i = 0; i < 2; i++) {
                int so = ob * 5120 + (a_row0 + 64 * i) * A_STRIDE + a_kk;
                *(uint4*)(dyn + SM_AH + so) = pAh[i];
                *(uint4*)(dyn + SM_AL + so) = pAl[i];
            }
            int sb = ob * 2304 + bk * B_STRIDE + bn;
            *(uint4*)(dyn + SM_BH + sb) = pBh;
            *(uint4*)(dyn + SM_BL + sb) = pBl;
            __syncthreads();
        }
    }

    // epilogue — writes bf16 hi/lo at stride PWc
    #pragma unroll
    for (int mi = 0; mi < 2; mi++)
        #pragma unroll
        for (int nj = 0; nj < 4; nj++) {
            int col = n0 + warp_n * 32 + nj * 8 + (lane & 3) * 2;
            if (col >= Fo) continue;
            float2 b2 = *(const float2*)(bias + col);
            #pragma unroll
            for (int half = 0; half < 2; half++) {
                int row = rbase + warp_m * 32 + mi * 16 + (lane >> 2) + half * 8;
                float vx = acc[mi][nj][half * 2 + 0] + b2.x;
                float vy = acc[mi][nj][half * 2 + 1] + b2.y;
                if (res) {
                    float2 r2 = *(const float2*)(res + (size_t)row * Fo + col);
                    vx += r2.x; vy += r2.y;
                }
                if (doRelu) { vx = fmaxf(vx, 0.0f); vy = fmaxf(vy, 0.0f); }
                __nv_bfloat16 hx, lx, hy, ly;
                split2(vx, hx, lx); split2(vy, hy, ly);
                *(__nv_bfloat162*)(Ch + (size_t)row * PWc + col) = __halves2bfloat162(hx, hy);
                *(__nv_bfloat162*)(Cl + (size_t)row * PWc + col) = __halves2bfloat162(lx, ly);
            }
        }
}

// ---------------- row squared norms from hi/lo bf16 --------------------------
__global__ void row_norms_hl(const __nv_bfloat16* __restrict__ H,
                             const __nv_bfloat16* __restrict__ L,
                             float* __restrict__ out, int D)
{
    int warp = (blockIdx.x * blockDim.x + threadIdx.x) >> 5;
    int lane = threadIdx.x & 31;
    if (warp >= NTOT) return;
    float s = 0.0f;
    for (int k = lane; k < D; k += 32) {
        size_t o = (size_t)warp * D + k;
        float v = __bfloat162float(H[o]) + __bfloat162float(L[o]);
        s += v * v;
    }
    #pragma unroll
    for (int o = 16; o; o >>= 1) s += __shfl_xor_sync(0xffffffffu, s, o);
    if (lane == 0) out[warp] = s;
}

// ---------------- fused fm kernel: MMA dots + fast-exp epilogue --------------
// CTA tile: 64 i-rows (X and paired Y) x 128 j-cols. 8 warps (2m x 4n), warp
// tile 32x32. f-dots K=112 (7 ksteps), g-dots K=32 (2 ksteps), hi/lo 3-pass.
#define FMI 64
#define FMJ 128
#define AF_S 120
#define BF_S 136
#define AG_S 40
// bf16-unit offsets in dynamic smem
#define OF_AXH 0
#define OF_AXL 7680
#define OF_AYH 15360
#define OF_AYL 23040
#define OF_BH  30720
#define OF_BL  45952
#define OG_AXH 0
#define OG_AXL 2560
#define OG_AYH 5120
#define OG_AYL 7680
#define OG_BH  10240
#define OG_BL  14592
#define FM_DYN_BYTES (61184 * 2)

__global__ __launch_bounds__(256)
void fm2_kernel(const float* __restrict__ eps_p, const float* __restrict__ sig_p,
                const float* __restrict__ sig0_p, const float* __restrict__ cst_p)
{
    extern __shared__ __nv_bfloat16 dynb[];
    __shared__ float nfx[64], nfy[64], ngx[64], ngy[64];
    __shared__ float nfv[128], ngv[128];
    __shared__ float scs[128];
    __shared__ float red[256];

    const int tid    = threadIdx.x;
    const int lane   = tid & 31;
    const int wid    = tid >> 5;
    const int warp_m = wid >> 2;      // 0..1
    const int warp_n = wid & 3;       // 0..3
    const int ibase  = blockIdx.y * FMI;
    const int jbase  = blockIdx.x * FMJ;
    const int XR = ibase, YR = NXC + ibase, VR = 2 * NXC + jbase;

    if (tid < 64) {
        nfx[tid] = g_nF[XR + tid]; nfy[tid] = g_nF[YR + tid];
        ngx[tid] = g_nG[XR + tid]; ngy[tid] = g_nG[YR + tid];
    } else if (tid < 192) {
        int j = tid - 64;
        nfv[j] = g_nF[VR + j]; ngv[j] = g_nG[VR + j];
    }
    if (tid < 128) scs[tid] = 0.0f;

    // ---- stage f tiles ----
    for (int e = tid; e < 896; e += 256) {           // A: 64 rows x 14 uint4
        int r = e / 14, kv = (e % 14) * 8;
        *(uint4*)&dynb[OF_AXH + r * AF_S + kv] = *(const uint4*)&g_Fh[(size_t)(XR + r) * FDP + kv];
        *(uint4*)&dynb[OF_AXL + r * AF_S + kv] = *(const uint4*)&g_Fl[(size_t)(XR + r) * FDP + kv];
        *(uint4*)&dynb[OF_AYH + r * AF_S + kv] = *(const uint4*)&g_Fh[(size_t)(YR + r) * FDP + kv];
        *(uint4*)&dynb[OF_AYL + r * AF_S + kv] = *(const uint4*)&g_Fl[(size_t)(YR + r) * FDP + kv];
    }
    for (int e = tid; e < 1792; e += 256) {          // B: V transposed to [k][n]
        int j = e / 14, kv = (e % 14) * 8;
        uint4 vh = *(const uint4*)&g_Fh[(size_t)(VR + j) * FDP + kv];
        uint4 vl = *(const uint4*)&g_Fl[(size_t)(VR + j) * FDP + kv];
        const __nv_bfloat16* ph = (const __nv_bfloat16*)&vh;
        const __nv_bfloat16* pl = (const __nv_bfloat16*)&vl;
        #pragma unroll
        for (int t = 0; t < 8; t++) {
            dynb[OF_BH + (kv + t) * BF_S + j] = ph[t];
            dynb[OF_BL + (kv + t) * BF_S + j] = pl[t];
        }
    }
    __syncthreads();

    const uint32_t dyn32 = smem_u32(dynb);
    const int a_row  = warp_m * 32 + (lane & 15);
    const int a_kadd = (lane >> 4) * 8;
    const int b_k    = lane & 15;
    const int b_n    = warp_n * 32 + ((lane & 16) ? 8 : 0);

    float accX[2][4][4], accY[2][4][4];
    #pragma unroll
    for (int i = 0; i < 2; i++)
        #pragma unroll
        for (int j = 0; j < 4; j++)
            #pragma unroll
            for (int q = 0; q < 4; q++) { accX[i][j][q] = 0.0f; accY[i][j][q] = 0.0f; }

    // ---- f-phase MMA: K = 112 ----
    #pragma unroll
    for (int ks = 0; ks < 7; ks++) {
        uint32_t AXh[2][4], AXl[2][4], AYh[2][4], AYl[2][4], Bh[2][4], Bl[2][4];
        #pragma unroll
        for (int mi = 0; mi < 2; mi++) {
            uint32_t ao = (uint32_t)((a_row + mi * 16) * AF_S + ks * 16 + a_kadd) * 2u;
            ldsm_x4(dyn32 + OF_AXH * 2u + ao, AXh[mi]);
            ldsm_x4(dyn32 + OF_AXL * 2u + ao, AXl[mi]);
            ldsm_x4(dyn32 + OF_AYH * 2u + ao, AYh[mi]);
            ldsm_x4(dyn32 + OF_AYL * 2u + ao, AYl[mi]);
        }
        #pragma unroll
        for (int np = 0; np < 2; np++) {
            uint32_t bo = (uint32_t)((b_k + ks * 16) * BF_S + b_n + np * 16) * 2u;
            ldsm_x4_t(dyn32 + OF_BH * 2u + bo, Bh[np]);
            ldsm_x4_t(dyn32 + OF_BL * 2u + bo, Bl[np]);
        }
        #pragma unroll
        for (int mi = 0; mi < 2; mi++)
            #pragma unroll
            for (int nj = 0; nj < 4; nj++) {
                const int np = nj >> 1, hf = (nj & 1) * 2;
                mma_bf16(accX[mi][nj], AXh[mi], Bh[np][hf], Bh[np][hf + 1]);
                mma_bf16(accX[mi][nj], AXh[mi], Bl[np][hf], Bl[np][hf + 1]);
                mma_bf16(accX[mi][nj], AXl[mi], Bh[np][hf], Bh[np][hf + 1]);
                mma_bf16(accY[mi][nj], AYh[mi], Bh[np][hf], Bh[np][hf + 1]);
                mma_bf16(accY[mi][nj], AYh[mi], Bl[np][hf], Bl[np][hf + 1]);
                mma_bf16(accY[mi][nj], AYl[mi], Bh[np][hf], Bh[np][hf + 1]);
            }
    }

    // ---- convert f-dots -> K-factor (in place) ----
    const float ep     = 1.0f / (1.0f + __expf(-eps_p[0]));
    const float inv_s  = 1.0f / (sig_p[0]  * sig_p[0]);
    const float inv_s0 = 1.0f / (sig0_p[0] * sig0_p[0]);
    const float cstv   = cst_p[0];
    const float one_ep = 1.0f - ep;

    #pragma unroll
    for (int mi = 0; mi < 2; mi++)
        #pragma unroll
        for (int nj = 0; nj < 4; nj++)
            #pragma unroll
            for (int q = 0; q < 4; q++) {
                int rl = warp_m * 32 + mi * 16 + (lane >> 2) + (q >> 1) * 8;
                int cl = warp_n * 32 + nj * 8 + (lane & 3) * 2 + (q & 1);
                float Dx = fmaxf(nfx[rl] + nfv[cl] - 2.0f * accX[mi][nj][q], 0.0f);
                float Dy = fmaxf(nfy[rl] + nfv[cl] - 2.0f * accY[mi][nj][q], 0.0f);
                accX[mi][nj][q] = fmaf(one_ep, fexp(-Dx * inv_s0), ep);
                accY[mi][nj][q] = fmaf(one_ep, fexp(-Dy * inv_s0), ep);
            }

    // ---- stage g tiles (reuse smem) ----
    __syncthreads();
    {
        int e = tid;   // A: 64 rows x 4 uint4 = 256 exactly
        int r = e >> 2, kv = (e & 3) * 8;
        *(uint4*)&dynb[OG_AXH + r * AG_S + kv] = *(const uint4*)&g_Gh[(size_t)(XR + r) * GDP + kv];
        *(uint4*)&dynb[OG_AXL + r * AG_S + kv] = *(const uint4*)&g_Gl[(size_t)(XR + r) * GDP + kv];
        *(uint4*)&dynb[OG_AYH + r * AG_S + kv] = *(const uint4*)&g_Gh[(size_t)(YR + r) * GDP + kv];
        *(uint4*)&dynb[OG_AYL + r * AG_S + kv] = *(const uint4*)&g_Gl[(size_t)(YR + r) * GDP + kv];
    }
    for (int e = tid; e < 512; e += 256) {          // B: 128 rows x 4 uint4
        int j = e >> 2, kv = (e & 3) * 8;
        uint4 vh = *(const uint4*)&g_Gh[(size_t)(VR + j) * GDP + kv];
        uint4 vl = *(const uint4*)&g_Gl[(size_t)(VR + j) * GDP + kv];
        const __nv_bfloat16* ph = (const __nv_bfloat16*)&vh;
        const __nv_bfloat16* pl = (const __nv_bfloat16*)&vl;
        #pragma unroll
        for (int t = 0; t < 8; t++) {
            dynb[OG_BH + (kv + t) * BF_S + j] = ph[t];
            dynb[OG_BL + (kv + t) * BF_S + j] = pl[t];
        }
    }
    __syncthreads();

    // ---- g-phase MMA: K = 32 ----
    float gX[2][4][4], gY[2][4][4];
    #pragma unroll
    for (int i = 0; i < 2; i++)
        #pragma unroll
        for (int j = 0; j < 4; j++)
            #pragma unroll
            for (int q = 0; q < 4; q++) { gX[i][j][q] = 0.0f; gY[i][j][q] = 0.0f; }

    #pragma unroll
    for (int ks = 0; ks < 2; ks++) {
        uint32_t AXh[2][4], AXl[2][4], AYh[2][4], AYl[2][4], Bh[2][4], Bl[2][4];
        #pragma unroll
        for (int mi = 0; mi < 2; mi++) {
            uint32_t ao = (uint32_t)((a_row + mi * 16) * AG_S + ks * 16 + a_kadd) * 2u;
            ldsm_x4(dyn32 + OG_AXH * 2u + ao, AXh[mi]);
            ldsm_x4(dyn32 + OG_AXL * 2u + ao, AXl[mi]);
            ldsm_x4(dyn32 + OG_AYH * 2u + ao, AYh[mi]);
            ldsm_x4(dyn32 + OG_AYL * 2u + ao, AYl[mi]);
        }
        #pragma unroll
        for (int np = 0; np < 2; np++) {
            uint32_t bo = (uint32_t)((b_k + ks * 16) * BF_S + b_n + np * 16) * 2u;
            ldsm_x4_t(dyn32 + OG_BH * 2u + bo, Bh[np]);
            ldsm_x4_t(dyn32 + OG_BL * 2u + bo, Bl[np]);
        }
        #pragma unroll
        for (int mi = 0; mi < 2; mi++)
            #pragma unroll
            for (int nj = 0; nj < 4; nj++) {
                const int np = nj >> 1, hf = (nj & 1) * 2;
                mma_bf16(gX[mi][nj], AXh[mi], Bh[np][hf], Bh[np][hf + 1]);
                mma_bf16(gX[mi][nj], AXh[mi], Bl[np][hf], Bl[np][hf + 1]);
                mma_bf16(gX[mi][nj], AXl[mi], Bh[np][hf], Bh[np][hf + 1]);
                mma_bf16(gY[mi][nj], AYh[mi], Bh[np][hf], Bh[np][hf + 1]);
                mma_bf16(gY[mi][nj], AYh[mi], Bl[np][hf], Bl[np][hf + 1]);
                mma_bf16(gY[mi][nj], AYl[mi], Bh[np][hf], Bh[np][hf + 1]);
            }
    }

    // ---- final epilogue: fm, colsum, sumsq ----
    const float RS = 0.03125f;    // 1/sqrt(1024)
    float csum[8];
    #pragma unroll
    for (int i = 0; i < 8; i++) csum[i] = 0.0f;
    float qacc = 0.0f;

    #pragma unroll
    for (int mi = 0; mi < 2; mi++)
        #pragma unroll
        for (int nj = 0; nj < 4; nj++) {
            float vq[4];
            #pragma unroll
            for (int q = 0; q < 4; q++) {
                int rl = warp_m * 32 + mi * 16 + (lane >> 2) + (q >> 1) * 8;
                int cl = warp_n * 32 + nj * 8 + (lane & 3) * 2 + (q & 1);
                float Dgx = fmaxf(ngx[rl] + ngv[cl] - 2.0f * gX[mi][nj][q], 0.0f);
                float Dgy = fmaxf(ngy[rl] + ngv[cl] - 2.0f * gY[mi][nj][q], 0.0f);
                float KX = cstv * accX[mi][nj][q] * fexp(-Dgx * inv_s);
                float KY = cstv * accY[mi][nj][q] * fexp(-Dgy * inv_s);
                float v = (KX - KY) * RS;
                vq[q] = v;
                csum[nj * 2 + (q & 1)] += v;
                qacc += v * v;
            }
            int colg = jbase + warp_n * 32 + nj * 8 + (lane & 3) * 2;
            int row0 = ibase + warp_m * 32 + mi * 16 + (lane >> 2);
            *(float2*)&g_fm[(size_t)row0 * JC + colg]       = make_float2(vq[0], vq[1]);
            *(float2*)&g_fm[(size_t)(row0 + 8) * JC + colg] = make_float2(vq[2], vq[3]);
        }

    #pragma unroll
    for (int c8 = 0; c8 < 8; c8++) {
        int cl = warp_n * 32 + (c8 >> 1) * 8 + (lane & 3) * 2 + (c8 & 1);
        atomicAdd(&scs[cl], csum[c8]);
    }
    red[tid] = qacc;
    __syncthreads();
    for (int s = 128; s; s >>= 1) {
        if (tid < s) red[tid] += red[tid + s];
        __syncthreads();
    }
    if (tid == 0) atomicAdd(&g_scal[0], red[0]);
    if (tid < 128) atomicAdd(&g_colsum[jbase + tid], scs[tid]);
}

// ---------------- mu + sum(mu^2) --------------------------------------------
__global__ void mu_kernel() {
    __shared__ float red[JC];
    int j = threadIdx.x;
    float m = g_colsum[j] * (1.0f / (float)NXC);
    g_mu[j] = m;
    red[j] = m * m;
    __syncthreads();
    for (int s = 512; s; s >>= 1) {
        if (j < s) red[j] += red[j + s];
        __syncthreads();
    }
    if (j == 0) g_scal[2] = red[0];
}

// ---------------- s_i = fm[i]·mu ; accumulate s_i^2 -------------------------
__global__ __launch_bounds__(256) void s2_kernel() {
    __shared__ float smu[JC];
    int tid = threadIdx.x;
    for (int e = tid; e < JC; e += 256) smu[e] = g_mu[e];
    __syncthreads();
    int row  = blockIdx.x * 8 + (tid >> 5);
    int lane = tid & 31;
    float s = 0.0f;
    #pragma unroll 4
    for (int t = 0; t < 32; t++) {
        int c = lane + 32 * t;
        s += g_fm[(size_t)row * JC + c] * smu[c];
    }
    #pragma unroll
    for (int o = 16; o; o >>= 1) s += __shfl_xor_sync(0xffffffffu, s, o);
    if (lane == 0) atomicAdd(&g_scal[1], s * s);
}

// ---------------- finalize (fp64 to kill cancellation) ----------------------
__global__ void finalize_kernel(float* out) {
    double sumfm2 = (double)g_scal[0];
    double sums2  = (double)g_scal[1];
    double summu2 = (double)g_scal[2];
    double nx = (double)NXC;
    double t1 = summu2 * (nx / (nx - 1.0));
    double t2 = sumfm2 / nx / (nx - 1.0);
    double mean = t1 - t2;
    double var  = 4.0 * (sums2 / nx) - 4.0 * summu2 * summu2;
    out[0] = (float)(-(mean / sqrt(var + 1e-6)));
}

// ---------------- launch -----------------------------------------------------
extern "C" void kernel_launch(void* const* d_in, const int* in_sizes, int n_in,
                              void* d_out, int out_size)
{
    const float* XY = (const float*)d_in[0];
    const float* V  = (const float*)d_in[1];
    const float *dnW[6], *dnb[6], *anW[6], *anb[6];
    for (int i = 0; i < 6; i++) {
        dnW[i] = (const float*)d_in[2 + 2 * i];
        dnb[i] = (const float*)d_in[3 + 2 * i];
        anW[i] = (const float*)d_in[14 + 2 * i];
        anb[i] = (const float*)d_in[15 + 2 * i];
    }
    const float* eps   = (const float*)d_in[26];
    const float* sig   = (const float*)d_in[27];
    const float* sig0  = (const float*)d_in[28];
    const float* cstp  = (const float*)d_in[29];

    float *in0, *nF, *nG;
    __nv_bfloat16 *inh, *inl, *h0, *l0, *h1, *l1, *Wh, *Wl, *Fh, *Fl, *Gh, *Gl;
    cudaGetSymbolAddress((void**)&in0, g_in0);
    cudaGetSymbolAddress((void**)&nF,  g_nF);
    cudaGetSymbolAddress((void**)&nG,  g_nG);
    cudaGetSymbolAddress((void**)&inh, g_inh);
    cudaGetSymbolAddress((void**)&inl, g_inl);
    cudaGetSymbolAddress((void**)&h0,  g_Ah0);
    cudaGetSymbolAddress((void**)&l0,  g_Al0);
    cudaGetSymbolAddress((void**)&h1,  g_Ah1);
    cudaGetSymbolAddress((void**)&l1,  g_Al1);
    cudaGetSymbolAddress((void**)&Wh,  g_Wh);
    cudaGetSymbolAddress((void**)&Wl,  g_Wl);
    cudaGetSymbolAddress((void**)&Fh,  g_Fh);
    cudaGetSymbolAddress((void**)&Fl,  g_Fl);
    cudaGetSymbolAddress((void**)&Gh,  g_Gh);
    cudaGetSymbolAddress((void**)&Gl,  g_Gl);

    const int GY = NTOT / BMM;                       // 520
    const dim3 blk(256);
    const dim3 gH((HC + BNN - 1) / BNN, GY);
    const dim3 gF((FD + BNN - 1) / BNN, GY);
    const dim3 gG((GD + BNN - 1) / BNN, GY);

    concat_kernel<<<(NTOT * DIMC + 255) / 256, 256>>>(XY, V);
    concat_split_kernel<<<(NTOT * 32 + 255) / 256, 256>>>(XY, V);
    pad_zero_kernel<<<(NTOT * (PWH - HC) + 255) / 256, 256>>>();
    pad_fg_kernel<<<(NTOT * 12 + 255) / 256, 256>>>();
    init_acc_kernel<<<1, 1024>>>();

    prep_w_kernel<<<(WOFF + 255) / 256, 256>>>(dnW[0], DIMC, HC, 0);
    prep_w_kernel<<<(WOFF + 255) / 256, 256>>>(dnW[1], HC,   HC, 1);
    prep_w_kernel<<<(WOFF + 255) / 256, 256>>>(dnW[2], HC,   HC, 2);
    prep_w_kernel<<<(WOFF + 255) / 256, 256>>>(dnW[3], HC,   HC, 3);
    prep_w_kernel<<<(WOFF + 255) / 256, 256>>>(dnW[4], HC,   HC, 4);
    prep_w_kernel<<<(WOFF + 255) / 256, 256>>>(dnW[5], HC,   FD, 5);
    prep_w_kernel<<<(WOFF + 255) / 256, 256>>>(anW[0], DIMC, HC, 6);
    prep_w_kernel<<<(WOFF + 255) / 256, 256>>>(anW[1], HC,   HC, 7);
    prep_w_kernel<<<(WOFF + 255) / 256, 256>>>(anW[2], HC,   HC, 8);
    prep_w_kernel<<<(WOFF + 255) / 256, 256>>>(anW[3], HC,   HC, 9);
    prep_w_kernel<<<(WOFF + 255) / 256, 256>>>(anW[4], HC,   HC, 10);
    prep_w_kernel<<<(WOFF + 255) / 256, 256>>>(anW[5], HC,   GD, 11);

    cudaFuncSetAttribute(mma_gemm2, cudaFuncAttributeMaxDynamicSharedMemorySize,
                         GEMM_SMEM_BYTES);
    #define GEMM(grid, Ahp, Alp, PWa, L, bias, Fo, Chp, Clp, PWc, resp, nC, relu) \
        mma_gemm2<<<grid, blk, GEMM_SMEM_BYTES>>>(Ahp, Alp, PWa, \
            Wh + (size_t)(L) * WOFF, Wl + (size_t)(L) * WOFF, bias, Fo, \
            Chp, Clp, PWc, resp, nC, relu)

    // dn MLP
    GEMM(gH, inh, inl, 32,  0, dnb[0], HC, h0, l0, PWH, (const float*)0, 1,  1);
    GEMM(gH, h0,  l0,  PWH, 1, dnb[1], HC, h1, l1, PWH, (const float*)0, 10, 1);
    GEMM(gH, h1,  l1,  PWH, 2, dnb[2], HC, h0, l0, PWH, (const float*)0, 10, 1);
    GEMM(gH, h0,  l0,  PWH, 3, dnb[3], HC, h1, l1, PWH, (const float*)0, 10, 1);
    GEMM(gH, h1,  l1,  PWH, 4, dnb[4], HC, h0, l0, PWH, (const float*)0, 10, 1);
    GEMM(gF, h0,  l0,  PWH, 5, dnb[5], FD, Fh, Fl, FDP, (const float*)0, 10, 0);

    // an MLP (residual on last layer)
    GEMM(gH, inh, inl, 32,  6, anb[0], HC, h1, l1, PWH, (const float*)0, 1,  1);
    GEMM(gH, h1,  l1,  PWH, 7, anb[1], HC, h0, l0, PWH, (const float*)0, 10, 1);
    GEMM(gH, h0,  l0,  PWH, 8, anb[2], HC, h1, l1, PWH, (const float*)0, 10, 1);
    GEMM(gH, h1,  l1,  PWH, 9, anb[3], HC, h0, l0, PWH, (const float*)0, 10, 1);
    GEMM(gH, h0,  l0,  PWH, 10, anb[4], HC, h1, l1, PWH, (const float*)0, 10, 1);
    GEMM(gG, h1,  l1,  PWH, 11, anb[5], GD, Gh, Gl, GDP, in0, 10, 0);

    // norms from hi/lo
    row_norms_hl<<<NTOT / 8, 256>>>(Fh, Fl, nF, FDP);
    row_norms_hl<<<NTOT / 8, 256>>>(Gh, Gl, nG, GDP);

    // fused fm (MMA dots + fast exp)
    cudaFuncSetAttribute(fm2_kernel, cudaFuncAttributeMaxDynamicSharedMemorySize,
                         FM_DYN_BYTES);
    fm2_kernel<<<dim3(JC / FMJ, NXC / FMI), 256, FM_DYN_BYTES>>>(eps, sig, sig0, cstp);

    mu_kernel<<<1, JC>>>();
    s2_kernel<<<NXC / 8, 256>>>();
    finalize_kernel<<<1, 1>>>((float*)d_out);
}

// round 6
// speedup vs baseline: 2.3328x; 1.1075x over previous
#include <cuda_runtime.h>
#include <cuda_bf16.h>
#include <math.h>
#include <stdint.h>

// Problem constants (fixed by the dataset)
#define NXC   32768
#define NTOT  66560
#define DIMC  28
#define HC    300
#define FD    100
#define GD    28
#define JC    1024

#define PWH   320
#define FDP   112
#define GDP   32
#define WOFF  (320 * 320)

// ---------------- scratch ----------------------------------------------------
__device__ float g_in0 [(size_t)NTOT * DIMC];
__device__ __align__(16) __nv_bfloat16 g_inh[(size_t)NTOT * 32];
__device__ __align__(16) __nv_bfloat16 g_inl[(size_t)NTOT * 32];
__device__ __align__(16) __nv_bfloat16 g_Ah0[(size_t)NTOT * PWH];
__device__ __align__(16) __nv_bfloat16 g_Al0[(size_t)NTOT * PWH];
__device__ __align__(16) __nv_bfloat16 g_Ah1[(size_t)NTOT * PWH];
__device__ __align__(16) __nv_bfloat16 g_Al1[(size_t)NTOT * PWH];
__device__ __align__(16) __nv_bfloat16 g_Wh[12 * WOFF];
__device__ __align__(16) __nv_bfloat16 g_Wl[12 * WOFF];
__device__ __align__(16) __nv_bfloat16 g_Fh[(size_t)NTOT * FDP];
__device__ __align__(16) __nv_bfloat16 g_Fl[(size_t)NTOT * FDP];
__device__ __align__(16) __nv_bfloat16 g_Gh[(size_t)NTOT * GDP];
__device__ __align__(16) __nv_bfloat16 g_Gl[(size_t)NTOT * GDP];
// V part of F/G pre-transposed to [k][1024] for cheap fm B staging
__device__ __align__(16) __nv_bfloat16 g_FvTh[FDP * JC];
__device__ __align__(16) __nv_bfloat16 g_FvTl[FDP * JC];
__device__ __align__(16) __nv_bfloat16 g_GvTh[GDP * JC];
__device__ __align__(16) __nv_bfloat16 g_GvTl[GDP * JC];
__device__ float g_nF  [NTOT];
__device__ float g_nG  [NTOT];
__device__ float g_fm  [(size_t)NXC * JC];
__device__ float g_colsum[JC];
__device__ float g_mu    [JC];
__device__ float g_scal  [8];

__device__ __forceinline__ void split2(float x, __nv_bfloat16& h, __nv_bfloat16& l) {
    h = __float2bfloat16(x);
    l = __float2bfloat16(x - __bfloat162float(h));
}
// MUFU-pipe exp2 (2-ulp); exp(-D*c) computed as ex2(-D*(c*log2e))
__device__ __forceinline__ float fexp2(float x) {
    float r;
    asm("ex2.approx.ftz.f32 %0, %1;" : "=f"(r) : "f"(x));
    return r;
}

// ---------------- prep kernels ----------------------------------------------
__global__ void concat_kernel(const float* __restrict__ XY, const float* __restrict__ V) {
    int t = blockIdx.x * blockDim.x + threadIdx.x;
    const int total = NTOT * DIMC;
    const int xyn   = 2 * NXC * DIMC;
    if (t >= total) return;
    g_in0[t] = (t < xyn) ? XY[t] : V[t - xyn];
}
__global__ void concat_split_kernel(const float* __restrict__ XY, const float* __restrict__ V) {
    int t = blockIdx.x * blockDim.x + threadIdx.x;
    if (t >= NTOT * 32) return;
    int r = t >> 5, c = t & 31;
    float v = 0.0f;
    if (c < DIMC) {
        int idx = r * DIMC + c;
        v = (r < 2 * NXC) ? XY[idx] : V[(r - 2 * NXC) * DIMC + c];
    }
    __nv_bfloat16 h, l; split2(v, h, l);
    g_inh[t] = h; g_inl[t] = l;
}
__global__ void pad_zero_kernel() {
    int t = blockIdx.x * blockDim.x + threadIdx.x;
    if (t >= NTOT * (PWH - HC)) return;
    int r = t / (PWH - HC), c = HC + t % (PWH - HC);
    size_t o = (size_t)r * PWH + c;
    __nv_bfloat16 z = __float2bfloat16(0.0f);
    g_Ah0[o] = z; g_Al0[o] = z; g_Ah1[o] = z; g_Al1[o] = z;
}
__global__ void pad_fg_kernel() {
    int t = blockIdx.x * blockDim.x + threadIdx.x;
    if (t >= NTOT * 12) return;
    int r = t / 12, c = t % 12;
    __nv_bfloat16 z = __float2bfloat16(0.0f);
    size_t of = (size_t)r * FDP + 100 + c;
    g_Fh[of] = z; g_Fl[of] = z;
    if (c < 4) {
        size_t og = (size_t)r * GDP + 28 + c;
        g_Gh[og] = z; g_Gl[og] = z;
    }
}
__global__ void init_acc_kernel() {
    int t = threadIdx.x;
    if (t < JC) g_colsum[t] = 0.0f;
    if (t < 8)  g_scal[t]   = 0.0f;
}
__global__ void prep_w_kernel(const float* __restrict__ W, int Fi, int Fo, int layer) {
    int idx = blockIdx.x * blockDim.x + threadIdx.x;
    if (idx >= WOFF) return;
    int k = idx / 320, n = idx - k * 320;
    float v = (k < Fi && n < Fo) ? W[(size_t)k * Fo + n] : 0.0f;
    __nv_bfloat16 h, l; split2(v, h, l);
    g_Wh[(size_t)layer * WOFF + idx] = h;
    g_Wl[(size_t)layer * WOFF + idx] = l;
}
// transpose V rows of F/G into [k][1024]
__global__ void transpose_v_kernel() {
    int t = blockIdx.x * blockDim.x + threadIdx.x;
    if (t < FDP * JC) {
        int k = t >> 10, j = t & 1023;
        size_t src = (size_t)(2 * NXC + j) * FDP + k;
        g_FvTh[t] = g_Fh[src];
        g_FvTl[t] = g_Fl[src];
    }
    if (t < GDP * JC) {
        int k = t >> 10, j = t & 1023;
        size_t src = (size_t)(2 * NXC + j) * GDP + k;
        g_GvTh[t] = g_Gh[src];
        g_GvTl[t] = g_Gl[src];
    }
}

// =============== shared MMA helpers ==========================================
__device__ __forceinline__ uint32_t smem_u32(const void* p) {
    uint32_t a;
    asm("{ .reg .u64 t; cvta.to.shared.u64 t, %1; cvt.u32.u64 %0, t; }" : "=r"(a) : "l"(p));
    return a;
}
__device__ __forceinline__ void ldsm_x4(uint32_t addr, uint32_t r[4]) {
    asm volatile("ldmatrix.sync.aligned.m8n8.x4.shared.b16 {%0,%1,%2,%3}, [%4];"
        : "=r"(r[0]), "=r"(r[1]), "=r"(r[2]), "=r"(r[3]) : "r"(addr));
}
__device__ __forceinline__ void ldsm_x4_t(uint32_t addr, uint32_t r[4]) {
    asm volatile("ldmatrix.sync.aligned.m8n8.x4.trans.shared.b16 {%0,%1,%2,%3}, [%4];"
        : "=r"(r[0]), "=r"(r[1]), "=r"(r[2]), "=r"(r[3]) : "r"(addr));
}
__device__ __forceinline__ void mma_bf16(float c[4], const uint32_t a[4],
                                         uint32_t b0, uint32_t b1) {
    asm volatile(
        "mma.sync.aligned.m16n8k16.row.col.f32.bf16.bf16.f32 "
        "{%0,%1,%2,%3}, {%4,%5,%6,%7}, {%8,%9}, {%0,%1,%2,%3};"
        : "+f"(c[0]), "+f"(c[1]), "+f"(c[2]), "+f"(c[3])
        : "r"(a[0]), "r"(a[1]), "r"(a[2]), "r"(a[3]), "r"(b0), "r"(b1));
}
#define CP_ASYNC16(dst_u32, src_ptr) \
    asm volatile("cp.async.cg.shared.global [%0], [%1], 16;" \
        :: "r"(dst_u32), "l"(src_ptr) : "memory")
#define CP_COMMIT() asm volatile("cp.async.commit_group;" ::: "memory")
#define CP_WAIT(n)  asm volatile("cp.async.wait_group %0;" :: "n"(n) : "memory")

// =============== bf16-split GEMM with cp.async double buffer =================
#define BMM 128
#define BNN 64
#define BKK 32
#define A_STRIDE 40
#define B_STRIDE 72
#define SM_AH 0
#define SM_AL 10240
#define SM_BH 20480
#define SM_BL 25088
#define GEMM_SMEM_BYTES (29696 * 2)

__global__ __launch_bounds__(256, 2)
void mma_gemm2(const __nv_bfloat16* __restrict__ Ah, const __nv_bfloat16* __restrict__ Al,
               int PWa,
               const __nv_bfloat16* __restrict__ Wh, const __nv_bfloat16* __restrict__ Wl,
               const float* __restrict__ bias, int Fo,
               __nv_bfloat16* __restrict__ Ch, __nv_bfloat16* __restrict__ Cl, int PWc,
               const float* __restrict__ res,
               int nC, int doRelu)
{
    extern __shared__ __nv_bfloat16 dyn[];

    const int tid    = threadIdx.x;
    const int lane   = tid & 31;
    const int wid    = tid >> 5;
    const int warp_m = wid >> 1;
    const int warp_n = wid & 1;
    const int rbase  = blockIdx.y * BMM;
    const int n0     = blockIdx.x * BNN;

    const int a_row0 = tid >> 2;
    const int a_kk   = (tid & 3) * 8;
    const int bk     = tid >> 3;
    const int bn     = (tid & 7) * 8;

    const uint32_t dyn32 = smem_u32(dyn);
    const int a_row  = warp_m * 32 + (lane & 15);
    const int a_kadd = (lane >> 4) * 8;
    const uint32_t aHiB = dyn32 + (uint32_t)(SM_AH + a_row * A_STRIDE + a_kadd) * 2u;
    const uint32_t aLoB = dyn32 + (uint32_t)(SM_AL + a_row * A_STRIDE + a_kadd) * 2u;
    const int b_k = (lane & 7) + ((lane & 8) ? 8 : 0);
    const int b_n = warp_n * 32 + ((lane & 16) ? 8 : 0);
    const uint32_t bHiB = dyn32 + (uint32_t)(SM_BH + b_k * B_STRIDE + b_n) * 2u;
    const uint32_t bLoB = dyn32 + (uint32_t)(SM_BL + b_k * B_STRIDE + b_n) * 2u;

    // cp.async destination bases (byte addresses)
    const uint32_t dA0 = dyn32 + (uint32_t)(a_row0 * A_STRIDE + a_kk) * 2u;
    const uint32_t dA1 = dyn32 + (uint32_t)((a_row0 + 64) * A_STRIDE + a_kk) * 2u;
    const uint32_t dB0 = dyn32 + (uint32_t)(SM_BH + bk * B_STRIDE + bn) * 2u;

    float acc[2][4][4];
    #pragma unroll
    for (int i = 0; i < 2; i++)
        #pragma unroll
        for (int j = 0; j < 4; j++)
            #pragma unroll
            for (int q = 0; q < 4; q++) acc[i][j][q] = 0.0f;

    // prologue: async-copy chunk 0 into buffer 0
    {
        size_t o0 = (size_t)(rbase + a_row0) * PWa + a_kk;
        size_t o1 = (size_t)(rbase + a_row0 + 64) * PWa + a_kk;
        CP_ASYNC16(dA0,            Ah + o0);
        CP_ASYNC16(dA0 + 20480u,   Al + o0);   // SM_AL*2
        CP_ASYNC16(dA1,            Ah + o1);
        CP_ASYNC16(dA1 + 20480u,   Al + o1);
        size_t bo = (size_t)bk * 320 + n0 + bn;
        CP_ASYNC16(dB0,            Wh + bo);
        CP_ASYNC16(dB0 + 9216u,    Wl + bo);   // (SM_BL-SM_BH)*2
        CP_COMMIT();
    }

    for (int c = 0; c < nC; c++) {
        const int buf = c & 1;
        const uint32_t aOff = (uint32_t)(buf * 5120 * 2);
        const uint32_t bOff = (uint32_t)(buf * 2304 * 2);

        if (c + 1 < nC) {
            const int k0 = (c + 1) * BKK;
            const uint32_t od = (uint32_t)(((c + 1) & 1) ? 10240 : 0);  // buf offset bytes (A)
            const uint32_t ob = (uint32_t)(((c + 1) & 1) ? 4608  : 0);  // buf offset bytes (B)
            size_t o0 = (size_t)(rbase + a_row0) * PWa + k0 + a_kk;
            size_t o1 = (size_t)(rbase + a_row0 + 64) * PWa + k0 + a_kk;
            CP_ASYNC16(dA0 + od,          Ah + o0);
            CP_ASYNC16(dA0 + od + 20480u, Al + o0);
            CP_ASYNC16(dA1 + od,          Ah + o1);
            CP_ASYNC16(dA1 + od + 20480u, Al + o1);
            size_t bo = (size_t)(k0 + bk) * 320 + n0 + bn;
            CP_ASYNC16(dB0 + ob,          Wh + bo);
            CP_ASYNC16(dB0 + ob + 9216u,  Wl + bo);
            CP_COMMIT();
            CP_WAIT(1);
        } else {
            CP_WAIT(0);
        }
        __syncthreads();

        #pragma unroll
        for (int ks = 0; ks < 2; ks++) {
            uint32_t Ahr[2][4], Alr[2][4], Bhr[2][4], Blr[2][4];
            #pragma unroll
            for (int mi = 0; mi < 2; mi++) {
                uint32_t off = aOff + (uint32_t)(mi * 16 * A_STRIDE + ks * 16) * 2u;
                ldsm_x4(aHiB + off, Ahr[mi]);
                ldsm_x4(aLoB + off, Alr[mi]);
            }
            #pragma unroll
            for (int np = 0; np < 2; np++) {
                uint32_t off = bOff + (uint32_t)(np * 16 + ks * 16 * B_STRIDE) * 2u;
                ldsm_x4_t(bHiB + off, Bhr[np]);
                ldsm_x4_t(bLoB + off, Blr[np]);
            }
            #pragma unroll
            for (int mi = 0; mi < 2; mi++)
                #pragma unroll
                for (int nj = 0; nj < 4; nj++) {
                    const int np = nj >> 1, hf = (nj & 1) * 2;
                    mma_bf16(acc[mi][nj], Ahr[mi], Bhr[np][hf], Bhr[np][hf + 1]);
                    mma_bf16(acc[mi][nj], Ahr[mi], Blr[np][hf], Blr[np][hf + 1]);
                    mma_bf16(acc[mi][nj], Alr[mi], Bhr[np][hf], Bhr[np][hf + 1]);
                }
        }
        __syncthreads();
    }

    // epilogue — writes bf16 hi/lo at stride PWc
    #pragma unroll
    for (int mi = 0; mi < 2; mi++)
        #pragma unroll
        for (int nj = 0; nj < 4; nj++) {
            int col = n0 + warp_n * 32 + nj * 8 + (lane & 3) * 2;
            if (col >= Fo) continue;
            float2 b2 = *(const float2*)(bias + col);
            #pragma unroll
            for (int half = 0; half < 2; half++) {
                int row = rbase + warp_m * 32 + mi * 16 + (lane >> 2) + half * 8;
                float vx = acc[mi][nj][half * 2 + 0] + b2.x;
                float vy = acc[mi][nj][half * 2 + 1] + b2.y;
                if (res) {
                    float2 r2 = *(const float2*)(res + (size_t)row * Fo + col);
                    vx += r2.x; vy += r2.y;
                }
                if (doRelu) { vx = fmaxf(vx, 0.0f); vy = fmaxf(vy, 0.0f); }
                __nv_bfloat16 hx, lx, hy, ly;
                split2(vx, hx, lx); split2(vy, hy, ly);
                *(__nv_bfloat162*)(Ch + (size_t)row * PWc + col) = __halves2bfloat162(hx, hy);
                *(__nv_bfloat162*)(Cl + (size_t)row * PWc + col) = __halves2bfloat162(lx, ly);
            }
        }
}

// ---------------- row squared norms from hi/lo bf16 --------------------------
__global__ void row_norms_hl(const __nv_bfloat16* __restrict__ H,
                             const __nv_bfloat16* __restrict__ L,
                             float* __restrict__ out, int D)
{
    int warp = (blockIdx.x * blockDim.x + threadIdx.x) >> 5;
    int lane = threadIdx.x & 31;
    if (warp >= NTOT) return;
    float s = 0.0f;
    for (int k = lane; k < D; k += 32) {
        size_t o = (size_t)warp * D + k;
        float v = __bfloat162float(H[o]) + __bfloat162float(L[o]);
        s += v * v;
    }
    #pragma unroll
    for (int o = 16; o; o >>= 1) s += __shfl_xor_sync(0xffffffffu, s, o);
    if (lane == 0) out[warp] = s;
}

// ---------------- fused fm kernel --------------------------------------------
#define FMI 64
#define FMJ 128
#define AF_S 120
#define BF_S 136
#define AG_S 40
#define OF_AXH 0
#define OF_AXL 7680
#define OF_AYH 15360
#define OF_AYL 23040
#define OF_BH  30720
#define OF_BL  45952
#define OG_AXH 0
#define OG_AXL 2560
#define OG_AYH 5120
#define OG_AYL 7680
#define OG_BH  10240
#define OG_BL  14592
#define FM_DYN_BYTES (61184 * 2)

__global__ __launch_bounds__(256)
void fm2_kernel(const float* __restrict__ eps_p, const float* __restrict__ sig_p,
                const float* __restrict__ sig0_p, const float* __restrict__ cst_p)
{
    extern __shared__ __nv_bfloat16 dynb[];
    __shared__ float nfx[64], nfy[64], ngx[64], ngy[64];
    __shared__ float nfv[128], ngv[128];
    __shared__ float scs[128];
    __shared__ float red[256];

    const int tid    = threadIdx.x;
    const int lane   = tid & 31;
    const int wid    = tid >> 5;
    const int warp_m = wid >> 2;
    const int warp_n = wid & 3;
    const int ibase  = blockIdx.y * FMI;
    const int jbase  = blockIdx.x * FMJ;
    const int XR = ibase, YR = NXC + ibase, VR = 2 * NXC + jbase;

    if (tid < 64) {
        nfx[tid] = g_nF[XR + tid]; nfy[tid] = g_nF[YR + tid];
        ngx[tid] = g_nG[XR + tid]; ngy[tid] = g_nG[YR + tid];
    } else if (tid < 192) {
        int j = tid - 64;
        nfv[j] = g_nF[VR + j]; ngv[j] = g_nG[VR + j];
    }
    if (tid < 128) scs[tid] = 0.0f;

    // ---- stage f tiles (all uint4 copies) ----
    for (int e = tid; e < 896; e += 256) {           // A: 64 rows x 14 uint4
        int r = e / 14, kv = (e % 14) * 8;
        *(uint4*)&dynb[OF_AXH + r * AF_S + kv] = *(const uint4*)&g_Fh[(size_t)(XR + r) * FDP + kv];
        *(uint4*)&dynb[OF_AXL + r * AF_S + kv] = *(const uint4*)&g_Fl[(size_t)(XR + r) * FDP + kv];
        *(uint4*)&dynb[OF_AYH + r * AF_S + kv] = *(const uint4*)&g_Fh[(size_t)(YR + r) * FDP + kv];
        *(uint4*)&dynb[OF_AYL + r * AF_S + kv] = *(const uint4*)&g_Fl[(size_t)(YR + r) * FDP + kv];
    }
    for (int e = tid; e < 1792; e += 256) {          // B from pre-transposed V: 112 k x 16 uint4
        int k = e >> 4, jv = (e & 15) * 8;
        *(uint4*)&dynb[OF_BH + k * BF_S + jv] = *(const uint4*)&g_FvTh[k * 1024 + jbase + jv];
        *(uint4*)&dynb[OF_BL + k * BF_S + jv] = *(const uint4*)&g_FvTl[k * 1024 + jbase + jv];
    }
    __syncthreads();

    const uint32_t dyn32 = smem_u32(dynb);
    const int a_row  = warp_m * 32 + (lane & 15);
    const int a_kadd = (lane >> 4) * 8;
    const int b_k    = lane & 15;
    const int b_n    = warp_n * 32 + ((lane & 16) ? 8 : 0);

    float accX[2][4][4], accY[2][4][4];
    #pragma unroll
    for (int i = 0; i < 2; i++)
        #pragma unroll
        for (int j = 0; j < 4; j++)
            #pragma unroll
            for (int q = 0; q < 4; q++) { accX[i][j][q] = 0.0f; accY[i][j][q] = 0.0f; }

    // ---- f-phase MMA: K = 112 ----
    #pragma unroll
    for (int ks = 0; ks < 7; ks++) {
        uint32_t AXh[2][4], AXl[2][4], AYh[2][4], AYl[2][4], Bh[2][4], Bl[2][4];
        #pragma unroll
        for (int mi = 0; mi < 2; mi++) {
            uint32_t ao = (uint32_t)((a_row + mi * 16) * AF_S + ks * 16 + a_kadd) * 2u;
            ldsm_x4(dyn32 + OF_AXH * 2u + ao, AXh[mi]);
            ldsm_x4(dyn32 + OF_AXL * 2u + ao, AXl[mi]);
            ldsm_x4(dyn32 + OF_AYH * 2u + ao, AYh[mi]);
            ldsm_x4(dyn32 + OF_AYL * 2u + ao, AYl[mi]);
        }
        #pragma unroll
        for (int np = 0; np < 2; np++) {
            uint32_t bo = (uint32_t)((b_k + ks * 16) * BF_S + b_n + np * 16) * 2u;
            ldsm_x4_t(dyn32 + OF_BH * 2u + bo, Bh[np]);
            ldsm_x4_t(dyn32 + OF_BL * 2u + bo, Bl[np]);
        }
        #pragma unroll
        for (int mi = 0; mi < 2; mi++)
            #pragma unroll
            for (int nj = 0; nj < 4; nj++) {
                const int np = nj >> 1, hf = (nj & 1) * 2;
                mma_bf16(accX[mi][nj], AXh[mi], Bh[np][hf], Bh[np][hf + 1]);
                mma_bf16(accX[mi][nj], AXh[mi], Bl[np][hf], Bl[np][hf + 1]);
                mma_bf16(accX[mi][nj], AXl[mi], Bh[np][hf], Bh[np][hf + 1]);
                mma_bf16(accY[mi][nj], AYh[mi], Bh[np][hf], Bh[np][hf + 1]);
                mma_bf16(accY[mi][nj], AYh[mi], Bl[np][hf], Bl[np][hf + 1]);
                mma_bf16(accY[mi][nj], AYl[mi], Bh[np][hf], Bh[np][hf + 1]);
            }
    }

    // ---- convert f-dots -> K-factor (MUFU exp2; log2e folded into constants) ----
    const float LOG2E  = 1.4426950408889634f;
    const float ep     = 1.0f / (1.0f + __expf(-eps_p[0]));
    const float is2    = LOG2E / (sig_p[0]  * sig_p[0]);
    const float is0    = LOG2E / (sig0_p[0] * sig0_p[0]);
    const float cstv   = cst_p[0];
    const float one_ep = 1.0f - ep;

    #pragma unroll
    for (int mi = 0; mi < 2; mi++)
        #pragma unroll
        for (int nj = 0; nj < 4; nj++)
            #pragma unroll
            for (int q = 0; q < 4; q++) {
                int rl = warp_m * 32 + mi * 16 + (lane >> 2) + (q >> 1) * 8;
                int cl = warp_n * 32 + nj * 8 + (lane & 3) * 2 + (q & 1);
                float Dx = fmaxf(nfx[rl] + nfv[cl] - 2.0f * accX[mi][nj][q], 0.0f);
                float Dy = fmaxf(nfy[rl] + nfv[cl] - 2.0f * accY[mi][nj][q], 0.0f);
                accX[mi][nj][q] = fmaf(one_ep, fexp2(-Dx * is0), ep);
                accY[mi][nj][q] = fmaf(one_ep, fexp2(-Dy * is0), ep);
            }

    // ---- stage g tiles ----
    __syncthreads();
    {
        int e = tid;
        int r = e >> 2, kv = (e & 3) * 8;
        *(uint4*)&dynb[OG_AXH + r * AG_S + kv] = *(const uint4*)&g_Gh[(size_t)(XR + r) * GDP + kv];
        *(uint4*)&dynb[OG_AXL + r * AG_S + kv] = *(const uint4*)&g_Gl[(size_t)(XR + r) * GDP + kv];
        *(uint4*)&dynb[OG_AYH + r * AG_S + kv] = *(const uint4*)&g_Gh[(size_t)(YR + r) * GDP + kv];
        *(uint4*)&dynb[OG_AYL + r * AG_S + kv] = *(const uint4*)&g_Gl[(size_t)(YR + r) * GDP + kv];
    }
    for (int e = tid; e < 512; e += 256) {           // B from pre-transposed GvT
        int k = e >> 4, jv = (e & 15) * 8;
        *(uint4*)&dynb[OG_BH + k * BF_S + jv] = *(const uint4*)&g_GvTh[k * 1024 + jbase + jv];
        *(uint4*)&dynb[OG_BL + k * BF_S + jv] = *(const uint4*)&g_GvTl[k * 1024 + jbase + jv];
    }
    __syncthreads();

    // ---- g-phase MMA: K = 32 ----
    float gX[2][4][4], gY[2][4][4];
    #pragma unroll
    for (int i = 0; i < 2; i++)
        #pragma unroll
        for (int j = 0; j < 4; j++)
            #pragma unroll
            for (int q = 0; q < 4; q++) { gX[i][j][q] = 0.0f; gY[i][j][q] = 0.0f; }

    #pragma unroll
    for (int ks = 0; ks < 2; ks++) {
        uint32_t AXh[2][4], AXl[2][4], AYh[2][4], AYl[2][4], Bh[2][4], Bl[2][4];
        #pragma unroll
        for (int mi = 0; mi < 2; mi++) {
            uint32_t ao = (uint32_t)((a_row + mi * 16) * AG_S + ks * 16 + a_kadd) * 2u;
            ldsm_x4(dyn32 + OG_AXH * 2u + ao, AXh[mi]);
            ldsm_x4(dyn32 + OG_AXL * 2u + ao, AXl[mi]);
            ldsm_x4(dyn32 + OG_AYH * 2u + ao, AYh[mi]);
            ldsm_x4(dyn32 + OG_AYL * 2u + ao, AYl[mi]);
        }
        #pragma unroll
        for (int np = 0; np < 2; np++) {
            uint32_t bo = (uint32_t)((b_k + ks * 16) * BF_S + b_n + np * 16) * 2u;
            ldsm_x4_t(dyn32 + OG_BH * 2u + bo, Bh[np]);
            ldsm_x4_t(dyn32 + OG_BL * 2u + bo, Bl[np]);
        }
        #pragma unroll
        for (int mi = 0; mi < 2; mi++)
            #pragma unroll
            for (int nj = 0; nj < 4; nj++) {
                const int np = nj >> 1, hf = (nj & 1) * 2;
                mma_bf16(gX[mi][nj], AXh[mi], Bh[np][hf], Bh[np][hf + 1]);
                mma_bf16(gX[mi][nj], AXh[mi], Bl[np][hf], Bl[np][hf + 1]);
                mma_bf16(gX[mi][nj], AXl[mi], Bh[np][hf], Bh[np][hf + 1]);
                mma_bf16(gY[mi][nj], AYh[mi], Bh[np][hf], Bh[np][hf + 1]);
                mma_bf16(gY[mi][nj], AYh[mi], Bl[np][hf], Bl[np][hf + 1]);
                mma_bf16(gY[mi][nj], AYl[mi], Bh[np][hf], Bh[np][hf + 1]);
            }
    }

    // ---- final epilogue ----
    const float RS = 0.03125f;
    float csum[8];
    #pragma unroll
    for (int i = 0; i < 8; i++) csum[i] = 0.0f;
    float qacc = 0.0f;

    #pragma unroll
    for (int mi = 0; mi < 2; mi++)
        #pragma unroll
        for (int nj = 0; nj < 4; nj++) {
            float vq[4];
            #pragma unroll
            for (int q = 0; q < 4; q++) {
                int rl = warp_m * 32 + mi * 16 + (lane >> 2) + (q >> 1) * 8;
                int cl = warp_n * 32 + nj * 8 + (lane & 3) * 2 + (q & 1);
                float Dgx = fmaxf(ngx[rl] + ngv[cl] - 2.0f * gX[mi][nj][q], 0.0f);
                float Dgy = fmaxf(ngy[rl] + ngv[cl] - 2.0f * gY[mi][nj][q], 0.0f);
                float KX = cstv * accX[mi][nj][q] * fexp2(-Dgx * is2);
                float KY = cstv * accY[mi][nj][q] * fexp2(-Dgy * is2);
                float v = (KX - KY) * RS;
                vq[q] = v;
                csum[nj * 2 + (q & 1)] += v;
                qacc += v * v;
            }
            int colg = jbase + warp_n * 32 + nj * 8 + (lane & 3) * 2;
            int row0 = ibase + warp_m * 32 + mi * 16 + (lane >> 2);
            *(float2*)&g_fm[(size_t)row0 * JC + colg]       = make_float2(vq[0], vq[1]);
            *(float2*)&g_fm[(size_t)(row0 + 8) * JC + colg] = make_float2(vq[2], vq[3]);
        }

    #pragma unroll
    for (int c8 = 0; c8 < 8; c8++) {
        int cl = warp_n * 32 + (c8 >> 1) * 8 + (lane & 3) * 2 + (c8 & 1);
        atomicAdd(&scs[cl], csum[c8]);
    }
    red[tid] = qacc;
    __syncthreads();
    for (int s = 128; s; s >>= 1) {
        if (tid < s) red[tid] += red[tid + s];
        __syncthreads();
    }
    if (tid == 0) atomicAdd(&g_scal[0], red[0]);
    if (tid < 128) atomicAdd(&g_colsum[jbase + tid], scs[tid]);
}

// ---------------- mu + sum(mu^2) ----------------------------------------------
__global__ void mu_kernel() {
    __shared__ float red[JC];
    int j = threadIdx.x;
    float m = g_colsum[j] * (1.0f / (float)NXC);
    g_mu[j] = m;
    red[j] = m * m;
    __syncthreads();
    for (int s = 512; s; s >>= 1) {
        if (j < s) red[j] += red[j + s];
        __syncthreads();
    }
    if (j == 0) g_scal[2] = red[0];
}

// ---------------- s_i = fm[i]·mu ; accumulate s_i^2 ---------------------------
__global__ __launch_bounds__(256) void s2_kernel() {
    __shared__ float smu[JC];
    int tid = threadIdx.x;
    for (int e = tid; e < JC; e += 256) smu[e] = g_mu[e];
    __syncthreads();
    int row  = blockIdx.x * 8 + (tid >> 5);
    int lane = tid & 31;
    float s = 0.0f;
    #pragma unroll 4
    for (int t = 0; t < 32; t++) {
        int c = lane + 32 * t;
        s += g_fm[(size_t)row * JC + c] * smu[c];
    }
    #pragma unroll
    for (int o = 16; o; o >>= 1) s += __shfl_xor_sync(0xffffffffu, s, o);
    if (lane == 0) atomicAdd(&g_scal[1], s * s);
}

// ---------------- finalize ------------------------------------------------------
__global__ void finalize_kernel(float* out) {
    double sumfm2 = (double)g_scal[0];
    double sums2  = (double)g_scal[1];
    double summu2 = (double)g_scal[2];
    double nx = (double)NXC;
    double t1 = summu2 * (nx / (nx - 1.0));
    double t2 = sumfm2 / nx / (nx - 1.0);
    double mean = t1 - t2;
    double var  = 4.0 * (sums2 / nx) - 4.0 * summu2 * summu2;
    out[0] = (float)(-(mean / sqrt(var + 1e-6)));
}

// ---------------- launch ---------------------------------------------------------
extern "C" void kernel_launch(void* const* d_in, const int* in_sizes, int n_in,
                              void* d_out, int out_size)
{
    const float* XY = (const float*)d_in[0];
    const float* V  = (const float*)d_in[1];
    const float *dnW[6], *dnb[6], *anW[6], *anb[6];
    for (int i = 0; i < 6; i++) {
        dnW[i] = (const float*)d_in[2 + 2 * i];
        dnb[i] = (const float*)d_in[3 + 2 * i];
        anW[i] = (const float*)d_in[14 + 2 * i];
        anb[i] = (const float*)d_in[15 + 2 * i];
    }
    const float* eps   = (const float*)d_in[26];
    const float* sig   = (const float*)d_in[27];
    const float* sig0  = (const float*)d_in[28];
    const float* cstp  = (const float*)d_in[29];

    float *in0, *nF, *nG;
    __nv_bfloat16 *inh, *inl, *h0, *l0, *h1, *l1, *Wh, *Wl, *Fh, *Fl, *Gh, *Gl;
    cudaGetSymbolAddress((void**)&in0, g_in0);
    cudaGetSymbolAddress((void**)&nF,  g_nF);
    cudaGetSymbolAddress((void**)&nG,  g_nG);
    cudaGetSymbolAddress((void**)&inh, g_inh);
    cudaGetSymbolAddress((void**)&inl, g_inl);
    cudaGetSymbolAddress((void**)&h0,  g_Ah0);
    cudaGetSymbolAddress((void**)&l0,  g_Al0);
    cudaGetSymbolAddress((void**)&h1,  g_Ah1);
    cudaGetSymbolAddress((void**)&l1,  g_Al1);
    cudaGetSymbolAddress((void**)&Wh,  g_Wh);
    cudaGetSymbolAddress((void**)&Wl,  g_Wl);
    cudaGetSymbolAddress((void**)&Fh,  g_Fh);
    cudaGetSymbolAddress((void**)&Fl,  g_Fl);
    cudaGetSymbolAddress((void**)&Gh,  g_Gh);
    cudaGetSymbolAddress((void**)&Gl,  g_Gl);

    const int GY = NTOT / BMM;
    const dim3 blk(256);
    const dim3 gH((HC + BNN - 1) / BNN, GY);
    const dim3 gF((FD + BNN - 1) / BNN, GY);
    const dim3 gG((GD + BNN - 1) / BNN, GY);

    concat_kernel<<<(NTOT * DIMC + 255) / 256, 256>>>(XY, V);
    concat_split_kernel<<<(NTOT * 32 + 255) / 256, 256>>>(XY, V);
    pad_zero_kernel<<<(NTOT * (PWH - HC) + 255) / 256, 256>>>();
    pad_fg_kernel<<<(NTOT * 12 + 255) / 256, 256>>>();
    init_acc_kernel<<<1, 1024>>>();

    prep_w_kernel<<<(WOFF + 255) / 256, 256>>>(dnW[0], DIMC, HC, 0);
    prep_w_kernel<<<(WOFF + 255) / 256, 256>>>(dnW[1], HC,   HC, 1);
    prep_w_kernel<<<(WOFF + 255) / 256, 256>>>(dnW[2], HC,   HC, 2);
    prep_w_kernel<<<(WOFF + 255) / 256, 256>>>(dnW[3], HC,   HC, 3);
    prep_w_kernel<<<(WOFF + 255) / 256, 256>>>(dnW[4], HC,   HC, 4);
    prep_w_kernel<<<(WOFF + 255) / 256, 256>>>(dnW[5], HC,   FD, 5);
    prep_w_kernel<<<(WOFF + 255) / 256, 256>>>(anW[0], DIMC, HC, 6);
    prep_w_kernel<<<(WOFF + 255) / 256, 256>>>(anW[1], HC,   HC, 7);
    prep_w_kernel<<<(WOFF + 255) / 256, 256>>>(anW[2], HC,   HC, 8);
    prep_w_kernel<<<(WOFF + 255) / 256, 256>>>(anW[3], HC,   HC, 9);
    prep_w_kernel<<<(WOFF + 255) / 256, 256>>>(anW[4], HC,   HC, 10);
    prep_w_kernel<<<(WOFF + 255) / 256, 256>>>(anW[5], HC,   GD, 11);

    cudaFuncSetAttribute(mma_gemm2, cudaFuncAttributeMaxDynamicSharedMemorySize,
                         GEMM_SMEM_BYTES);
    #define GEMM(grid, Ahp, Alp, PWa, L, bias, Fo, Chp, Clp, PWc, resp, nC, relu) \
        mma_gemm2<<<grid, blk, GEMM_SMEM_BYTES>>>(Ahp, Alp, PWa, \
            Wh + (size_t)(L) * WOFF, Wl + (size_t)(L) * WOFF, bias, Fo, \
            Chp, Clp, PWc, resp, nC, relu)

    // dn MLP
    GEMM(gH, inh, inl, 32,  0, dnb[0], HC, h0, l0, PWH, (const float*)0, 1,  1);
    GEMM(gH, h0,  l0,  PWH, 1, dnb[1], HC, h1, l1, PWH, (const float*)0, 10, 1);
    GEMM(gH, h1,  l1,  PWH, 2, dnb[2], HC, h0, l0, PWH, (const float*)0, 10, 1);
    GEMM(gH, h0,  l0,  PWH, 3, dnb[3], HC, h1, l1, PWH, (const float*)0, 10, 1);
    GEMM(gH, h1,  l1,  PWH, 4, dnb[4], HC, h0, l0, PWH, (const float*)0, 10, 1);
    GEMM(gF, h0,  l0,  PWH, 5, dnb[5], FD, Fh, Fl, FDP, (const float*)0, 10, 0);

    // an MLP (residual on last layer)
    GEMM(gH, inh, inl, 32,  6, anb[0], HC, h1, l1, PWH, (const float*)0, 1,  1);
    GEMM(gH, h1,  l1,  PWH, 7, anb[1], HC, h0, l0, PWH, (const float*)0, 10, 1);
    GEMM(gH, h0,  l0,  PWH, 8, anb[2], HC, h1, l1, PWH, (const float*)0, 10, 1);
    GEMM(gH, h1,  l1,  PWH, 9, anb[3], HC, h0, l0, PWH, (const float*)0, 10, 1);
    GEMM(gH, h0,  l0,  PWH, 10, anb[4], HC, h1, l1, PWH, (const float*)0, 10, 1);
    GEMM(gG, h1,  l1,  PWH, 11, anb[5], GD, Gh, Gl, GDP, in0, 10, 0);

    // V transpose + norms
    transpose_v_kernel<<<(FDP * JC + 255) / 256, 256>>>();
    row_norms_hl<<<NTOT / 8, 256>>>(Fh, Fl, nF, FDP);
    row_norms_hl<<<NTOT / 8, 256>>>(Gh, Gl, nG, GDP);

    // fused fm
    cudaFuncSetAttribute(fm2_kernel, cudaFuncAttributeMaxDynamicSharedMemorySize,
                         FM_DYN_BYTES);
    fm2_kernel<<<dim3(JC / FMJ, NXC / FMI), 256, FM_DYN_BYTES>>>(eps, sig, sig0, cstp);

    mu_kernel<<<1, JC>>>();
    s2_kernel<<<NXC / 8, 256>>>();
    finalize_kernel<<<1, 1>>>((float*)d_out);
}

// round 7
// speedup vs baseline: 2.4981x; 1.0709x over previous
#include <cuda_runtime.h>
#include <cuda_bf16.h>
#include <math.h>
#include <stdint.h>

// Problem constants
#define NXC   32768
#define NTOT  66560
#define DIMC  28
#define HC    300
#define FD    100
#define GD    28
#define JC    1024

#define PWH   320
#define FDP   112
#define GDP   32
#define WOFF  (320 * 320)

// ---------------- scratch ----------------------------------------------------
__device__ float g_in0 [(size_t)NTOT * DIMC];
__device__ __align__(16) __nv_bfloat16 g_inh[(size_t)NTOT * 32];
__device__ __align__(16) __nv_bfloat16 g_inl[(size_t)NTOT * 32];
// dn ping-pong
__device__ __align__(16) __nv_bfloat16 g_Ah0[(size_t)NTOT * PWH];
__device__ __align__(16) __nv_bfloat16 g_Al0[(size_t)NTOT * PWH];
__device__ __align__(16) __nv_bfloat16 g_Ah1[(size_t)NTOT * PWH];
__device__ __align__(16) __nv_bfloat16 g_Al1[(size_t)NTOT * PWH];
// an ping-pong
__device__ __align__(16) __nv_bfloat16 g_Bh0[(size_t)NTOT * PWH];
__device__ __align__(16) __nv_bfloat16 g_Bl0[(size_t)NTOT * PWH];
__device__ __align__(16) __nv_bfloat16 g_Bh1[(size_t)NTOT * PWH];
__device__ __align__(16) __nv_bfloat16 g_Bl1[(size_t)NTOT * PWH];
__device__ __align__(16) __nv_bfloat16 g_Wh[12 * WOFF];
__device__ __align__(16) __nv_bfloat16 g_Wl[12 * WOFF];
__device__ __align__(16) __nv_bfloat16 g_Fh[(size_t)NTOT * FDP];
__device__ __align__(16) __nv_bfloat16 g_Fl[(size_t)NTOT * FDP];
__device__ __align__(16) __nv_bfloat16 g_Gh[(size_t)NTOT * GDP];
__device__ __align__(16) __nv_bfloat16 g_Gl[(size_t)NTOT * GDP];
__device__ __align__(16) __nv_bfloat16 g_FvTh[FDP * JC];
__device__ __align__(16) __nv_bfloat16 g_FvTl[FDP * JC];
__device__ __align__(16) __nv_bfloat16 g_GvTh[GDP * JC];
__device__ __align__(16) __nv_bfloat16 g_GvTl[GDP * JC];
__device__ float g_nF  [NTOT];
__device__ float g_nG  [NTOT];
__device__ float g_fm  [(size_t)NXC * JC];
__device__ float g_colsum[JC];
__device__ float g_mu    [JC];
__device__ float g_scal  [8];

__device__ __forceinline__ void split2(float x, __nv_bfloat16& h, __nv_bfloat16& l) {
    h = __float2bfloat16(x);
    l = __float2bfloat16(x - __bfloat162float(h));
}
__device__ __forceinline__ float fexp2(float x) {
    float r;
    asm("ex2.approx.ftz.f32 %0, %1;" : "=f"(r) : "f"(x));
    return r;
}

// ---------------- prep kernels ----------------------------------------------
__global__ void concat_kernel(const float* __restrict__ XY, const float* __restrict__ V) {
    int t = blockIdx.x * blockDim.x + threadIdx.x;
    const int total = NTOT * DIMC;
    const int xyn   = 2 * NXC * DIMC;
    if (t >= total) return;
    g_in0[t] = (t < xyn) ? XY[t] : V[t - xyn];
}
__global__ void concat_split_kernel(const float* __restrict__ XY, const float* __restrict__ V) {
    int t = blockIdx.x * blockDim.x + threadIdx.x;
    if (t >= NTOT * 32) return;
    int r = t >> 5, c = t & 31;
    float v = 0.0f;
    if (c < DIMC) {
        int idx = r * DIMC + c;
        v = (r < 2 * NXC) ? XY[idx] : V[(r - 2 * NXC) * DIMC + c];
    }
    __nv_bfloat16 h, l; split2(v, h, l);
    g_inh[t] = h; g_inl[t] = l;
}
__global__ void pad_zero_kernel() {
    int t = blockIdx.x * blockDim.x + threadIdx.x;
    if (t >= NTOT * (PWH - HC)) return;
    int r = t / (PWH - HC), c = HC + t % (PWH - HC);
    size_t o = (size_t)r * PWH + c;
    __nv_bfloat16 z = __float2bfloat16(0.0f);
    g_Ah0[o] = z; g_Al0[o] = z; g_Ah1[o] = z; g_Al1[o] = z;
    g_Bh0[o] = z; g_Bl0[o] = z; g_Bh1[o] = z; g_Bl1[o] = z;
}
__global__ void pad_fg_kernel() {
    int t = blockIdx.x * blockDim.x + threadIdx.x;
    if (t >= NTOT * 12) return;
    int r = t / 12, c = t % 12;
    __nv_bfloat16 z = __float2bfloat16(0.0f);
    size_t of = (size_t)r * FDP + 100 + c;
    g_Fh[of] = z; g_Fl[of] = z;
    if (c < 4) {
        size_t og = (size_t)r * GDP + 28 + c;
        g_Gh[og] = z; g_Gl[og] = z;
    }
}
__global__ void init_acc_kernel() {
    int t = threadIdx.x;
    if (t < JC) g_colsum[t] = 0.0f;
    if (t < 8)  g_scal[t]   = 0.0f;
}
struct WPrepArgs {
    const float* W[12];
    int Fi[12];
    int Fo[12];
};
__global__ void prep_w_all(WPrepArgs a) {
    int layer = blockIdx.y;
    int idx = blockIdx.x * blockDim.x + threadIdx.x;
    if (idx >= WOFF) return;
    int k = idx / 320, n = idx - k * 320;
    int Fi = a.Fi[layer], Fo = a.Fo[layer];
    float v = (k < Fi && n < Fo) ? a.W[layer][(size_t)k * Fo + n] : 0.0f;
    __nv_bfloat16 h, l; split2(v, h, l);
    g_Wh[(size_t)layer * WOFF + idx] = h;
    g_Wl[(size_t)layer * WOFF + idx] = l;
}
__global__ void transpose_v_kernel() {
    int t = blockIdx.x * blockDim.x + threadIdx.x;
    if (t < FDP * JC) {
        int k = t >> 10, j = t & 1023;
        size_t src = (size_t)(2 * NXC + j) * FDP + k;
        g_FvTh[t] = g_Fh[src];
        g_FvTl[t] = g_Fl[src];
    }
    if (t < GDP * JC) {
        int k = t >> 10, j = t & 1023;
        size_t src = (size_t)(2 * NXC + j) * GDP + k;
        g_GvTh[t] = g_Gh[src];
        g_GvTl[t] = g_Gl[src];
    }
}

// =============== shared MMA helpers ==========================================
__device__ __forceinline__ uint32_t smem_u32(const void* p) {
    uint32_t a;
    asm("{ .reg .u64 t; cvta.to.shared.u64 t, %1; cvt.u32.u64 %0, t; }" : "=r"(a) : "l"(p));
    return a;
}
__device__ __forceinline__ void ldsm_x4(uint32_t addr, uint32_t r[4]) {
    asm volatile("ldmatrix.sync.aligned.m8n8.x4.shared.b16 {%0,%1,%2,%3}, [%4];"
        : "=r"(r[0]), "=r"(r[1]), "=r"(r[2]), "=r"(r[3]) : "r"(addr));
}
__device__ __forceinline__ void ldsm_x4_t(uint32_t addr, uint32_t r[4]) {
    asm volatile("ldmatrix.sync.aligned.m8n8.x4.trans.shared.b16 {%0,%1,%2,%3}, [%4];"
        : "=r"(r[0]), "=r"(r[1]), "=r"(r[2]), "=r"(r[3]) : "r"(addr));
}
__device__ __forceinline__ void mma_bf16(float c[4], const uint32_t a[4],
                                         uint32_t b0, uint32_t b1) {
    asm volatile(
        "mma.sync.aligned.m16n8k16.row.col.f32.bf16.bf16.f32 "
        "{%0,%1,%2,%3}, {%4,%5,%6,%7}, {%8,%9}, {%0,%1,%2,%3};"
        : "+f"(c[0]), "+f"(c[1]), "+f"(c[2]), "+f"(c[3])
        : "r"(a[0]), "r"(a[1]), "r"(a[2]), "r"(a[3]), "r"(b0), "r"(b1));
}
#define CP_ASYNC16(dst_u32, src_ptr) \
    asm volatile("cp.async.cg.shared.global [%0], [%1], 16;" \
        :: "r"(dst_u32), "l"(src_ptr) : "memory")
#define CP_COMMIT() asm volatile("cp.async.commit_group;" ::: "memory")
#define CP_WAIT(n)  asm volatile("cp.async.wait_group %0;" :: "n"(n) : "memory")

// =============== bf16-split GEMM, 3-stage cp.async, dn+an batched ============
#define BMM 128
#define BNN 64
#define BKK 32
#define A_STRIDE 40
#define B_STRIDE 72
// 3 stages: AH 3x5120, AL 3x5120, BH 3x2304, BL 3x2304 (bf16 units)
#define SM_AH 0
#define SM_AL 15360
#define SM_BH 30720
#define SM_BL 37632
#define GEMM_SMEM_BYTES 89088

__global__ __launch_bounds__(256, 2)
void mma_gemm3(const __nv_bfloat16* __restrict__ AhD, const __nv_bfloat16* __restrict__ AlD,
               const __nv_bfloat16* __restrict__ AhA, const __nv_bfloat16* __restrict__ AlA,
               int PWa,
               const __nv_bfloat16* __restrict__ WhB, const __nv_bfloat16* __restrict__ WlB,
               int layer,
               const float* __restrict__ biasD, const float* __restrict__ biasA,
               int FoD, int FoA,
               __nv_bfloat16* __restrict__ ChD, __nv_bfloat16* __restrict__ ClD,
               __nv_bfloat16* __restrict__ ChA, __nv_bfloat16* __restrict__ ClA,
               int PWcD, int PWcA,
               const float* __restrict__ resA,
               int nC, int doRelu)
{
    extern __shared__ __nv_bfloat16 dyn[];

    const int net = blockIdx.z;
    const __nv_bfloat16* Ah = net ? AhA : AhD;
    const __nv_bfloat16* Al = net ? AlA : AlD;
    const __nv_bfloat16* Wh = WhB + (size_t)(layer + 6 * net) * WOFF;
    const __nv_bfloat16* Wl = WlB + (size_t)(layer + 6 * net) * WOFF;
    const float* bias = net ? biasA : biasD;
    const int Fo  = net ? FoA : FoD;
    __nv_bfloat16* Ch = net ? ChA : ChD;
    __nv_bfloat16* Cl = net ? ClA : ClD;
    const int PWc = net ? PWcA : PWcD;
    const float* res = net ? resA : (const float*)0;

    const int n0 = blockIdx.x * BNN;
    if (n0 >= Fo) return;   // uniform per CTA

    const int tid    = threadIdx.x;
    const int lane   = tid & 31;
    const int wid    = tid >> 5;
    const int warp_m = wid >> 1;
    const int warp_n = wid & 1;
    const int rbase  = blockIdx.y * BMM;

    const int a_row0 = tid >> 2;
    const int a_kk   = (tid & 3) * 8;
    const int bk     = tid >> 3;
    const int bn     = (tid & 7) * 8;

    const uint32_t dyn32 = smem_u32(dyn);
    const int a_row  = warp_m * 32 + (lane & 15);
    const int a_kadd = (lane >> 4) * 8;
    const uint32_t aHiB = dyn32 + (uint32_t)(SM_AH + a_row * A_STRIDE + a_kadd) * 2u;
    const uint32_t aLoB = dyn32 + (uint32_t)(SM_AL + a_row * A_STRIDE + a_kadd) * 2u;
    const int b_k = (lane & 7) + ((lane & 8) ? 8 : 0);
    const int b_n = warp_n * 32 + ((lane & 16) ? 8 : 0);
    const uint32_t bHiB = dyn32 + (uint32_t)(SM_BH + b_k * B_STRIDE + b_n) * 2u;
    const uint32_t bLoB = dyn32 + (uint32_t)(SM_BL + b_k * B_STRIDE + b_n) * 2u;

    const uint32_t dA0 = dyn32 + (uint32_t)(a_row0 * A_STRIDE + a_kk) * 2u;
    const uint32_t dA1 = dyn32 + (uint32_t)((a_row0 + 64) * A_STRIDE + a_kk) * 2u;
    const uint32_t dB0 = dyn32 + (uint32_t)(SM_BH + bk * B_STRIDE + bn) * 2u;

    float acc[2][4][4];
    #pragma unroll
    for (int i = 0; i < 2; i++)
        #pragma unroll
        for (int j = 0; j < 4; j++)
            #pragma unroll
            for (int q = 0; q < 4; q++) acc[i][j][q] = 0.0f;

    #define ISSUE_CHUNK(k0, bf) do { \
        uint32_t od = (uint32_t)(bf) * 10240u; \
        uint32_t ob = (uint32_t)(bf) * 4608u; \
        size_t o0 = (size_t)(rbase + a_row0) * PWa + (k0) + a_kk; \
        size_t o1 = (size_t)(rbase + a_row0 + 64) * PWa + (k0) + a_kk; \
        CP_ASYNC16(dA0 + od,           Ah + o0); \
        CP_ASYNC16(dA0 + od + 30720u,  Al + o0); \
        CP_ASYNC16(dA1 + od,           Ah + o1); \
        CP_ASYNC16(dA1 + od + 30720u,  Al + o1); \
        size_t bo = (size_t)((k0) + bk) * 320 + n0 + bn; \
        CP_ASYNC16(dB0 + ob,           Wh + bo); \
        CP_ASYNC16(dB0 + ob + 13824u,  Wl + bo); \
        CP_COMMIT(); \
    } while (0)

    ISSUE_CHUNK(0, 0);
    if (nC > 1) ISSUE_CHUNK(32, 1);

    for (int c = 0; c < nC; c++) {
        const int buf = c % 3;
        const uint32_t aOff = (uint32_t)buf * 10240u;
        const uint32_t bOff = (uint32_t)buf * 4608u;

        if (c + 2 < nC) { ISSUE_CHUNK((c + 2) * BKK, (c + 2) % 3); CP_WAIT(2); }
        else if (c + 1 < nC) { CP_WAIT(1); }
        else { CP_WAIT(0); }
        __syncthreads();

        #pragma unroll
        for (int ks = 0; ks < 2; ks++) {
            uint32_t Ahr[2][4], Alr[2][4], Bhr[2][4], Blr[2][4];
            #pragma unroll
            for (int mi = 0; mi < 2; mi++) {
                uint32_t off = aOff + (uint32_t)(mi * 16 * A_STRIDE + ks * 16) * 2u;
                ldsm_x4(aHiB + off, Ahr[mi]);
                ldsm_x4(aLoB + off, Alr[mi]);
            }
            #pragma unroll
            for (int np = 0; np < 2; np++) {
                uint32_t off = bOff + (uint32_t)(np * 16 + ks * 16 * B_STRIDE) * 2u;
                ldsm_x4_t(bHiB + off, Bhr[np]);
                ldsm_x4_t(bLoB + off, Blr[np]);
            }
            #pragma unroll
            for (int mi = 0; mi < 2; mi++)
                #pragma unroll
                for (int nj = 0; nj < 4; nj++) {
                    const int np = nj >> 1, hf = (nj & 1) * 2;
                    mma_bf16(acc[mi][nj], Ahr[mi], Bhr[np][hf], Bhr[np][hf + 1]);
                    mma_bf16(acc[mi][nj], Ahr[mi], Blr[np][hf], Blr[np][hf + 1]);
                    mma_bf16(acc[mi][nj], Alr[mi], Bhr[np][hf], Bhr[np][hf + 1]);
                }
        }
        __syncthreads();
    }
    #undef ISSUE_CHUNK

    // epilogue
    #pragma unroll
    for (int mi = 0; mi < 2; mi++)
        #pragma unroll
        for (int nj = 0; nj < 4; nj++) {
            int col = n0 + warp_n * 32 + nj * 8 + (lane & 3) * 2;
            if (col >= Fo) continue;
            float2 b2 = *(const float2*)(bias + col);
            #pragma unroll
            for (int half = 0; half < 2; half++) {
                int row = rbase + warp_m * 32 + mi * 16 + (lane >> 2) + half * 8;
                float vx = acc[mi][nj][half * 2 + 0] + b2.x;
                float vy = acc[mi][nj][half * 2 + 1] + b2.y;
                if (res) {
                    float2 r2 = *(const float2*)(res + (size_t)row * Fo + col);
                    vx += r2.x; vy += r2.y;
                }
                if (doRelu) { vx = fmaxf(vx, 0.0f); vy = fmaxf(vy, 0.0f); }
                __nv_bfloat16 hx, lx, hy, ly;
                split2(vx, hx, lx); split2(vy, hy, ly);
                *(__nv_bfloat162*)(Ch + (size_t)row * PWc + col) = __halves2bfloat162(hx, hy);
                *(__nv_bfloat162*)(Cl + (size_t)row * PWc + col) = __halves2bfloat162(lx, ly);
            }
        }
}

// ---------------- row squared norms from hi/lo bf16 --------------------------
__global__ void row_norms_hl(const __nv_bfloat16* __restrict__ H,
                             const __nv_bfloat16* __restrict__ L,
                             float* __restrict__ out, int D)
{
    int warp = (blockIdx.x * blockDim.x + threadIdx.x) >> 5;
    int lane = threadIdx.x & 31;
    if (warp >= NTOT) return;
    float s = 0.0f;
    for (int k = lane; k < D; k += 32) {
        size_t o = (size_t)warp * D + k;
        float v = __bfloat162float(H[o]) + __bfloat162float(L[o]);
        s += v * v;
    }
    #pragma unroll
    for (int o = 16; o; o >>= 1) s += __shfl_xor_sync(0xffffffffu, s, o);
    if (lane == 0) out[warp] = s;
}

// ---------------- fused fm kernel: 512 threads, 16 warps ---------------------
#define FMI 64
#define FMJ 128
#define AF_S 120
#define BF_S 136
#define AG_S 40
#define OF_AXH 0
#define OF_AXL 7680
#define OF_AYH 15360
#define OF_AYL 23040
#define OF_BH  30720
#define OF_BL  45952
#define OG_AXH 0
#define OG_AXL 2560
#define OG_AYH 5120
#define OG_AYL 7680
#define OG_BH  10240
#define OG_BL  14592
#define FM_DYN_BYTES (61184 * 2)

__global__ __launch_bounds__(512)
void fm2_kernel(const float* __restrict__ eps_p, const float* __restrict__ sig_p,
                const float* __restrict__ sig0_p, const float* __restrict__ cst_p)
{
    extern __shared__ __nv_bfloat16 dynb[];
    __shared__ float nfx[64], nfy[64], ngx[64], ngy[64];
    __shared__ float nfv[128], ngv[128];
    __shared__ float scs[128];
    __shared__ float red[512];

    const int tid    = threadIdx.x;
    const int lane   = tid & 31;
    const int wid    = tid >> 5;          // 0..15
    const int warp_m = wid >> 3;          // 0..1
    const int warp_n = wid & 7;           // 0..7 (16 cols each)
    const int ibase  = blockIdx.y * FMI;
    const int jbase  = blockIdx.x * FMJ;
    const int XR = ibase, YR = NXC + ibase, VR = 2 * NXC + jbase;

    if (tid < 64) {
        nfx[tid] = g_nF[XR + tid]; nfy[tid] = g_nF[YR + tid];
        ngx[tid] = g_nG[XR + tid]; ngy[tid] = g_nG[YR + tid];
    } else if (tid < 192) {
        int j = tid - 64;
        nfv[j] = g_nF[VR + j]; ngv[j] = g_nG[VR + j];
    } else if (tid < 320) {
        scs[tid - 192] = 0.0f;
    }

    // ---- stage f tiles ----
    for (int e = tid; e < 896; e += 512) {
        int r = e / 14, kv = (e % 14) * 8;
        *(uint4*)&dynb[OF_AXH + r * AF_S + kv] = *(const uint4*)&g_Fh[(size_t)(XR + r) * FDP + kv];
        *(uint4*)&dynb[OF_AXL + r * AF_S + kv] = *(const uint4*)&g_Fl[(size_t)(XR + r) * FDP + kv];
        *(uint4*)&dynb[OF_AYH + r * AF_S + kv] = *(const uint4*)&g_Fh[(size_t)(YR + r) * FDP + kv];
        *(uint4*)&dynb[OF_AYL + r * AF_S + kv] = *(const uint4*)&g_Fl[(size_t)(YR + r) * FDP + kv];
    }
    for (int e = tid; e < 1792; e += 512) {
        int k = e >> 4, jv = (e & 15) * 8;
        *(uint4*)&dynb[OF_BH + k * BF_S + jv] = *(const uint4*)&g_FvTh[k * 1024 + jbase + jv];
        *(uint4*)&dynb[OF_BL + k * BF_S + jv] = *(const uint4*)&g_FvTl[k * 1024 + jbase + jv];
    }
    __syncthreads();

    const uint32_t dyn32 = smem_u32(dynb);
    const int a_row  = warp_m * 32 + (lane & 15);
    const int a_kadd = (lane >> 4) * 8;
    const int b_k    = lane & 15;
    const int b_n    = warp_n * 16 + ((lane & 16) ? 8 : 0);

    float accX[2][2][4], accY[2][2][4];
    #pragma unroll
    for (int i = 0; i < 2; i++)
        #pragma unroll
        for (int j = 0; j < 2; j++)
            #pragma unroll
            for (int q = 0; q < 4; q++) { accX[i][j][q] = 0.0f; accY[i][j][q] = 0.0f; }

    // ---- f-phase MMA: K = 112 ----
    #pragma unroll
    for (int ks = 0; ks < 7; ks++) {
        uint32_t AXh[2][4], AXl[2][4], AYh[2][4], AYl[2][4], Bh[4], Bl[4];
        #pragma unroll
        for (int mi = 0; mi < 2; mi++) {
            uint32_t ao = (uint32_t)((a_row + mi * 16) * AF_S + ks * 16 + a_kadd) * 2u;
            ldsm_x4(dyn32 + OF_AXH * 2u + ao, AXh[mi]);
            ldsm_x4(dyn32 + OF_AXL * 2u + ao, AXl[mi]);
            ldsm_x4(dyn32 + OF_AYH * 2u + ao, AYh[mi]);
            ldsm_x4(dyn32 + OF_AYL * 2u + ao, AYl[mi]);
        }
        {
            uint32_t bo = (uint32_t)((b_k + ks * 16) * BF_S + b_n) * 2u;
            ldsm_x4_t(dyn32 + OF_BH * 2u + bo, Bh);
            ldsm_x4_t(dyn32 + OF_BL * 2u + bo, Bl);
        }
        #pragma unroll
        for (int mi = 0; mi < 2; mi++)
            #pragma unroll
            for (int nj = 0; nj < 2; nj++) {
                const int hf = nj * 2;
                mma_bf16(accX[mi][nj], AXh[mi], Bh[hf], Bh[hf + 1]);
                mma_bf16(accX[mi][nj], AXh[mi], Bl[hf], Bl[hf + 1]);
                mma_bf16(accX[mi][nj], AXl[mi], Bh[hf], Bh[hf + 1]);
                mma_bf16(accY[mi][nj], AYh[mi], Bh[hf], Bh[hf + 1]);
                mma_bf16(accY[mi][nj], AYh[mi], Bl[hf], Bl[hf + 1]);
                mma_bf16(accY[mi][nj], AYl[mi], Bh[hf], Bh[hf + 1]);
            }
    }

    // ---- convert f-dots -> K-factor ----
    const float LOG2E  = 1.4426950408889634f;
    const float ep     = 1.0f / (1.0f + __expf(-eps_p[0]));
    const float is2    = LOG2E / (sig_p[0]  * sig_p[0]);
    const float is0    = LOG2E / (sig0_p[0] * sig0_p[0]);
    const float cstv   = cst_p[0];
    const float one_ep = 1.0f - ep;

    #pragma unroll
    for (int mi = 0; mi < 2; mi++)
        #pragma unroll
        for (int nj = 0; nj < 2; nj++)
            #pragma unroll
            for (int q = 0; q < 4; q++) {
                int rl = warp_m * 32 + mi * 16 + (lane >> 2) + (q >> 1) * 8;
                int cl = warp_n * 16 + nj * 8 + (lane & 3) * 2 + (q & 1);
                float Dx = fmaxf(nfx[rl] + nfv[cl] - 2.0f * accX[mi][nj][q], 0.0f);
                float Dy = fmaxf(nfy[rl] + nfv[cl] - 2.0f * accY[mi][nj][q], 0.0f);
                accX[mi][nj][q] = fmaf(one_ep, fexp2(-Dx * is0), ep);
                accY[mi][nj][q] = fmaf(one_ep, fexp2(-Dy * is0), ep);
            }

    // ---- stage g tiles ----
    __syncthreads();
    if (tid < 256) {
        int r = tid >> 2, kv = (tid & 3) * 8;
        *(uint4*)&dynb[OG_AXH + r * AG_S + kv] = *(const uint4*)&g_Gh[(size_t)(XR + r) * GDP + kv];
        *(uint4*)&dynb[OG_AXL + r * AG_S + kv] = *(const uint4*)&g_Gl[(size_t)(XR + r) * GDP + kv];
        *(uint4*)&dynb[OG_AYH + r * AG_S + kv] = *(const uint4*)&g_Gh[(size_t)(YR + r) * GDP + kv];
        *(uint4*)&dynb[OG_AYL + r * AG_S + kv] = *(const uint4*)&g_Gl[(size_t)(YR + r) * GDP + kv];
    }
    {
        int k = tid >> 4, jv = (tid & 15) * 8;
        *(uint4*)&dynb[OG_BH + k * BF_S + jv] = *(const uint4*)&g_GvTh[k * 1024 + jbase + jv];
        *(uint4*)&dynb[OG_BL + k * BF_S + jv] = *(const uint4*)&g_GvTl[k * 1024 + jbase + jv];
    }
    __syncthreads();

    // ---- g-phase MMA: K = 32 ----
    float gX[2][2][4], gY[2][2][4];
    #pragma unroll
    for (int i = 0; i < 2; i++)
        #pragma unroll
        for (int j = 0; j < 2; j++)
            #pragma unroll
            for (int q = 0; q < 4; q++) { gX[i][j][q] = 0.0f; gY[i][j][q] = 0.0f; }

    #pragma unroll
    for (int ks = 0; ks < 2; ks++) {
        uint32_t AXh[2][4], AXl[2][4], AYh[2][4], AYl[2][4], Bh[4], Bl[4];
        #pragma unroll
        for (int mi = 0; mi < 2; mi++) {
            uint32_t ao = (uint32_t)((a_row + mi * 16) * AG_S + ks * 16 + a_kadd) * 2u;
            ldsm_x4(dyn32 + OG_AXH * 2u + ao, AXh[mi]);
            ldsm_x4(dyn32 + OG_AXL * 2u + ao, AXl[mi]);
            ldsm_x4(dyn32 + OG_AYH * 2u + ao, AYh[mi]);
            ldsm_x4(dyn32 + OG_AYL * 2u + ao, AYl[mi]);
        }
        {
            uint32_t bo = (uint32_t)((b_k + ks * 16) * BF_S + b_n) * 2u;
            ldsm_x4_t(dyn32 + OG_BH * 2u + bo, Bh);
            ldsm_x4_t(dyn32 + OG_BL * 2u + bo, Bl);
        }
        #pragma unroll
        for (int mi = 0; mi < 2; mi++)
            #pragma unroll
            for (int nj = 0; nj < 2; nj++) {
                const int hf = nj * 2;
                mma_bf16(gX[mi][nj], AXh[mi], Bh[hf], Bh[hf + 1]);
                mma_bf16(gX[mi][nj], AXh[mi], Bl[hf], Bl[hf + 1]);
                mma_bf16(gX[mi][nj], AXl[mi], Bh[hf], Bh[hf + 1]);
                mma_bf16(gY[mi][nj], AYh[mi], Bh[hf], Bh[hf + 1]);
                mma_bf16(gY[mi][nj], AYh[mi], Bl[hf], Bl[hf + 1]);
                mma_bf16(gY[mi][nj], AYl[mi], Bh[hf], Bh[hf + 1]);
            }
    }

    // ---- final epilogue ----
    const float RS = 0.03125f;
    float csum[4];
    #pragma unroll
    for (int i = 0; i < 4; i++) csum[i] = 0.0f;
    float qacc = 0.0f;

    #pragma unroll
    for (int mi = 0; mi < 2; mi++)
        #pragma unroll
        for (int nj = 0; nj < 2; nj++) {
            float vq[4];
            #pragma unroll
            for (int q = 0; q < 4; q++) {
                int rl = warp_m * 32 + mi * 16 + (lane >> 2) + (q >> 1) * 8;
                int cl = warp_n * 16 + nj * 8 + (lane & 3) * 2 + (q & 1);
                float Dgx = fmaxf(ngx[rl] + ngv[cl] - 2.0f * gX[mi][nj][q], 0.0f);
                float Dgy = fmaxf(ngy[rl] + ngv[cl] - 2.0f * gY[mi][nj][q], 0.0f);
                float KX = cstv * accX[mi][nj][q] * fexp2(-Dgx * is2);
                float KY = cstv * accY[mi][nj][q] * fexp2(-Dgy * is2);
                float v = (KX - KY) * RS;
                vq[q] = v;
                csum[nj * 2 + (q & 1)] += v;
                qacc += v * v;
            }
            int colg = jbase + warp_n * 16 + nj * 8 + (lane & 3) * 2;
            int row0 = ibase + warp_m * 32 + mi * 16 + (lane >> 2);
            *(float2*)&g_fm[(size_t)row0 * JC + colg]       = make_float2(vq[0], vq[1]);
            *(float2*)&g_fm[(size_t)(row0 + 8) * JC + colg] = make_float2(vq[2], vq[3]);
        }

    #pragma unroll
    for (int c4 = 0; c4 < 4; c4++) {
        int cl = warp_n * 16 + (c4 >> 1) * 8 + (lane & 3) * 2 + (c4 & 1);
        atomicAdd(&scs[cl], csum[c4]);
    }
    red[tid] = qacc;
    __syncthreads();
    for (int s = 256; s; s >>= 1) {
        if (tid < s) red[tid] += red[tid + s];
        __syncthreads();
    }
    if (tid == 0) atomicAdd(&g_scal[0], red[0]);
    if (tid < 128) atomicAdd(&g_colsum[jbase + tid], scs[tid]);
}

// ---------------- mu + sum(mu^2) ----------------------------------------------
__global__ void mu_kernel() {
    __shared__ float red[JC];
    int j = threadIdx.x;
    float m = g_colsum[j] * (1.0f / (float)NXC);
    g_mu[j] = m;
    red[j] = m * m;
    __syncthreads();
    for (int s = 512; s; s >>= 1) {
        if (j < s) red[j] += red[j + s];
        __syncthreads();
    }
    if (j == 0) g_scal[2] = red[0];
}

// ---------------- s_i = fm[i]·mu ; accumulate s_i^2 ---------------------------
__global__ __launch_bounds__(256) void s2_kernel() {
    __shared__ float smu[JC];
    int tid = threadIdx.x;
    for (int e = tid; e < JC; e += 256) smu[e] = g_mu[e];
    __syncthreads();
    int row  = blockIdx.x * 8 + (tid >> 5);
    int lane = tid & 31;
    float s = 0.0f;
    #pragma unroll 4
    for (int t = 0; t < 32; t++) {
        int c = lane + 32 * t;
        s += g_fm[(size_t)row * JC + c] * smu[c];
    }
    #pragma unroll
    for (int o = 16; o; o >>= 1) s += __shfl_xor_sync(0xffffffffu, s, o);
    if (lane == 0) atomicAdd(&g_scal[1], s * s);
}

// ---------------- finalize ------------------------------------------------------
__global__ void finalize_kernel(float* out) {
    double sumfm2 = (double)g_scal[0];
    double sums2  = (double)g_scal[1];
    double summu2 = (double)g_scal[2];
    double nx = (double)NXC;
    double t1 = summu2 * (nx / (nx - 1.0));
    double t2 = sumfm2 / nx / (nx - 1.0);
    double mean = t1 - t2;
    double var  = 4.0 * (sums2 / nx) - 4.0 * summu2 * summu2;
    out[0] = (float)(-(mean / sqrt(var + 1e-6)));
}

// ---------------- launch ---------------------------------------------------------
extern "C" void kernel_launch(void* const* d_in, const int* in_sizes, int n_in,
                              void* d_out, int out_size)
{
    const float* XY = (const float*)d_in[0];
    const float* V  = (const float*)d_in[1];
    const float *dnW[6], *dnb[6], *anW[6], *anb[6];
    for (int i = 0; i < 6; i++) {
        dnW[i] = (const float*)d_in[2 + 2 * i];
        dnb[i] = (const float*)d_in[3 + 2 * i];
        anW[i] = (const float*)d_in[14 + 2 * i];
        anb[i] = (const float*)d_in[15 + 2 * i];
    }
    const float* eps   = (const float*)d_in[26];
    const float* sig   = (const float*)d_in[27];
    const float* sig0  = (const float*)d_in[28];
    const float* cstp  = (const float*)d_in[29];

    float *in0, *nF, *nG;
    __nv_bfloat16 *inh, *inl, *h0, *l0, *h1, *l1, *b0h, *b0l, *b1h, *b1l;
    __nv_bfloat16 *Wh, *Wl, *Fh, *Fl, *Gh, *Gl;
    cudaGetSymbolAddress((void**)&in0, g_in0);
    cudaGetSymbolAddress((void**)&nF,  g_nF);
    cudaGetSymbolAddress((void**)&nG,  g_nG);
    cudaGetSymbolAddress((void**)&inh, g_inh);
    cudaGetSymbolAddress((void**)&inl, g_inl);
    cudaGetSymbolAddress((void**)&h0,  g_Ah0);
    cudaGetSymbolAddress((void**)&l0,  g_Al0);
    cudaGetSymbolAddress((void**)&h1,  g_Ah1);
    cudaGetSymbolAddress((void**)&l1,  g_Al1);
    cudaGetSymbolAddress((void**)&b0h, g_Bh0);
    cudaGetSymbolAddress((void**)&b0l, g_Bl0);
    cudaGetSymbolAddress((void**)&b1h, g_Bh1);
    cudaGetSymbolAddress((void**)&b1l, g_Bl1);
    cudaGetSymbolAddress((void**)&Wh,  g_Wh);
    cudaGetSymbolAddress((void**)&Wl,  g_Wl);
    cudaGetSymbolAddress((void**)&Fh,  g_Fh);
    cudaGetSymbolAddress((void**)&Fl,  g_Fl);
    cudaGetSymbolAddress((void**)&Gh,  g_Gh);
    cudaGetSymbolAddress((void**)&Gl,  g_Gl);

    const int GY = NTOT / BMM;     // 520
    const dim3 blk(256);

    concat_kernel<<<(NTOT * DIMC + 255) / 256, 256>>>(XY, V);
    concat_split_kernel<<<(NTOT * 32 + 255) / 256, 256>>>(XY, V);
    pad_zero_kernel<<<(NTOT * (PWH - HC) + 255) / 256, 256>>>();
    pad_fg_kernel<<<(NTOT * 12 + 255) / 256, 256>>>();
    init_acc_kernel<<<1, 1024>>>();

    WPrepArgs wa;
    for (int i = 0; i < 6; i++) {
        wa.W[i]     = dnW[i];  wa.W[i + 6] = anW[i];
        wa.Fi[i]    = (i == 0) ? DIMC : HC;
        wa.Fi[i+6]  = (i == 0) ? DIMC : HC;
        wa.Fo[i]    = (i == 5) ? FD : HC;
        wa.Fo[i+6]  = (i == 5) ? GD : HC;
    }
    prep_w_all<<<dim3((WOFF + 255) / 256, 12), 256>>>(wa);

    cudaFuncSetAttribute(mma_gemm3, cudaFuncAttributeMaxDynamicSharedMemorySize,
                         GEMM_SMEM_BYTES);
    const dim3 gH(5, GY, 2);   // layers 0-4 (both nets Fo=300)
    const dim3 gL5(2, GY, 2);  // layer 5 (dn Fo=100 -> 2 blocks; an Fo=28 -> 1)

    #define GEMM3(grid, AhD,AlD,AhA,AlA, PWa, L, bD,bA, FoD,FoA, ChD,ClD,ChA,ClA, PWcD,PWcA, resA, nC, relu) \
        mma_gemm3<<<grid, blk, GEMM_SMEM_BYTES>>>(AhD,AlD,AhA,AlA, PWa, Wh, Wl, L, \
            bD,bA, FoD,FoA, ChD,ClD,ChA,ClA, PWcD,PWcA, resA, nC, relu)

    // L0: in -> (h0 / b0)
    GEMM3(gH, inh,inl, inh,inl, 32, 0, dnb[0],anb[0], HC,HC, h0,l0, b0h,b0l, PWH,PWH, (const float*)0, 1, 1);
    // L1: (h0/b0) -> (h1/b1)
    GEMM3(gH, h0,l0, b0h,b0l, PWH, 1, dnb[1],anb[1], HC,HC, h1,l1, b1h,b1l, PWH,PWH, (const float*)0, 10, 1);
    // L2
    GEMM3(gH, h1,l1, b1h,b1l, PWH, 2, dnb[2],anb[2], HC,HC, h0,l0, b0h,b0l, PWH,PWH, (const float*)0, 10, 1);
    // L3
    GEMM3(gH, h0,l0, b0h,b0l, PWH, 3, dnb[3],anb[3], HC,HC, h1,l1, b1h,b1l, PWH,PWH, (const float*)0, 10, 1);
    // L4
    GEMM3(gH, h1,l1, b1h,b1l, PWH, 4, dnb[4],anb[4], HC,HC, h0,l0, b0h,b0l, PWH,PWH, (const float*)0, 10, 1);
    // L5: dn -> F (Fo=100), an -> G (Fo=28, residual in0)
    GEMM3(gL5, h0,l0, b0h,b0l, PWH, 5, dnb[5],anb[5], FD,GD, Fh,Fl, Gh,Gl, FDP,GDP, in0, 10, 0);

    transpose_v_kernel<<<(FDP * JC + 255) / 256, 256>>>();
    row_norms_hl<<<NTOT / 8, 256>>>(Fh, Fl, nF, FDP);
    row_norms_hl<<<NTOT / 8, 256>>>(Gh, Gl, nG, GDP);

    cudaFuncSetAttribute(fm2_kernel, cudaFuncAttributeMaxDynamicSharedMemorySize,
                         FM_DYN_BYTES);
    fm2_kernel<<<dim3(JC / FMJ, NXC / FMI), 512, FM_DYN_BYTES>>>(eps, sig, sig0, cstp);

    mu_kernel<<<1, JC>>>();
    s2_kernel<<<NXC / 8, 256>>>();
    finalize_kernel<<<1, 1>>>((float*)d_out);
}